// round 12
// baseline (speedup 1.0000x reference)
#include <cuda_runtime.h>

// Fused 2-block tiny-transformer, 131072 sequences. One warp = TWO batches
// packed as f32x2. Split-half (dual-output partials + shfl_xor(16) combine)
// applied to: block1 FFN2, block1 out-proj, block2 FFN2, block2 out-proj.
// Block 2 is CLS-specialized; V kept in registers.

namespace {
constexpr int S  = 11;
constexpr int NW = 16;
constexpr int THREADS = NW * 32;                  // 512
constexpr int BTOT = 131072;
constexpr int NPAIR = BTOT / 2;                   // 65536

// --- per-block weight layout (floats), output-major rows, stride%32==4 ------
constexpr int QKVW_STR = 36;
constexpr int OUTW_STR = 36;
constexpr int W1_STR   = 36;
constexpr int W2_STR   = 132;

constexpr int O_QKVW = 0;
constexpr int O_QKVB = O_QKVW + 96 * QKVW_STR;    // 3456
constexpr int O_OUTW = O_QKVB + 96;               // 3552
constexpr int O_OUTB = O_OUTW + 32 * OUTW_STR;    // 4704
constexpr int O_LNAG = O_OUTB + 32;
constexpr int O_LNAB = O_LNAG + 32;
constexpr int O_W1   = O_LNAB + 32;               // 4800
constexpr int O_B1   = O_W1 + 128 * W1_STR;       // 9408
constexpr int O_W2   = O_B1 + 128;                // 9536
constexpr int O_B2   = O_W2 + 32 * W2_STR;        // 13760
constexpr int O_LNBG = O_B2 + 32;
constexpr int O_LNBB = O_LNBG + 32;
constexpr int BLK_SZ = O_LNBB + 32;               // 13856

// --- global smem layout (floats) ---
constexpr int O_WFEAT = 0;
constexpr int O_BFEAT = O_WFEAT + 320;
constexpr int O_CLS   = O_BFEAT + 320;
constexpr int O_CLFW  = O_CLS + 32;
constexpr int O_CLFB  = O_CLFW + 32;
constexpr int O_BLKW  = 720;
constexpr int O_ACT   = O_BLKW + BLK_SZ;          // 14576

// per-warp activation region (floats)
constexpr int H2_F   = 12 * 32 * 2;               // h2 [12][32] float2 = 768
// block1 staging (float2 units): q[11][16], k[11][16], v[11][16], ctx[11][34]
constexpr int F2_QS  = 0;
constexpr int F2_KS  = 176;
constexpr int F2_VS  = 352;
constexpr int F2_CTX = 528;
constexpr int CTX_STR = 34;
constexpr int LN_MU  = 374;                       // mu/sig offset in LN buf
// block2 staging (float2 units): q0[32], k[11][32], ctx[32]
constexpr int F2_Q2  = 0;
constexpr int F2_K2  = 32;
constexpr int F2_C2  = 736;
constexpr int F2_G2  = 0;                         // ffn g buffer (reuse)
constexpr int STG_F2 = 928;
constexpr int ACT_F  = H2_F + STG_F2 * 2;         // 2624 floats / warp
constexpr int SMEM_FLOATS = O_ACT + NW * ACT_F;   // 56560
constexpr int SMEM_BYTES  = SMEM_FLOATS * 4;      // 226240
}

extern __shared__ float smem[];

using u64 = unsigned long long;

static __device__ __forceinline__ u64 pack2(float x, float y) {
    u64 r; asm("mov.b64 %0,{%1,%2};" : "=l"(r) : "f"(x), "f"(y)); return r;
}
static __device__ __forceinline__ void unpack2(u64 v, float& x, float& y) {
    asm("mov.b64 {%0,%1},%2;" : "=f"(x), "=f"(y) : "l"(v));
}
static __device__ __forceinline__ u64 dup2(float x) { return pack2(x, x); }
static __device__ __forceinline__ u64 fma2(u64 a, u64 b, u64 c) {
    u64 d; asm("fma.rn.f32x2 %0,%1,%2,%3;" : "=l"(d) : "l"(a), "l"(b), "l"(c)); return d;
}
static __device__ __forceinline__ u64 add2(u64 a, u64 b) {
    u64 d; asm("add.rn.f32x2 %0,%1,%2;" : "=l"(d) : "l"(a), "l"(b)); return d;
}
static __device__ __forceinline__ u64 mul2(u64 a, u64 b) {
    u64 d; asm("mul.rn.f32x2 %0,%1,%2;" : "=l"(d) : "l"(a), "l"(b)); return d;
}
static __device__ __forceinline__ u64 neg2(u64 x) {
    return x ^ 0x8000000080000000ULL;
}
static __device__ __forceinline__ u64 shflx2(u64 v, int m) {
    float x, y; unpack2(v, x, y);
    x = __shfl_xor_sync(0xffffffffu, x, m);
    y = __shfl_xor_sync(0xffffffffu, y, m);
    return pack2(x, y);
}
static __device__ __forceinline__ float gelu1(float x) {
    return 0.5f * x * (1.0f + erff(x * 0.7071067811865475f));
}
// single-token LN via butterfly (block 2)
static __device__ __forceinline__ u64 ln_norm(u64 v, u64 lg, u64 lb) {
    u64 sum = v, sq = mul2(v, v);
#pragma unroll
    for (int mk = 16; mk; mk >>= 1) {
        sum = add2(sum, shflx2(sum, mk));
        sq  = add2(sq,  shflx2(sq,  mk));
    }
    float s0, s1, q0, q1, v0, v1;
    unpack2(sum, s0, s1); unpack2(sq, q0, q1); unpack2(v, v0, v1);
    float mu0 = s0 * 0.03125f, mu1 = s1 * 0.03125f;
    float r0 = rsqrtf(fmaf(-mu0, mu0, q0 * 0.03125f) + 1e-5f);
    float r1 = rsqrtf(fmaf(-mu1, mu1, q1 * 0.03125f) + 1e-5f);
    return fma2(pack2((v0 - mu0) * r0, (v1 - mu1) * r1), lg, lb);
}

struct KParams {
    const float* in[30];
    float* out;
};

// Staged LayerNorm over SN tokens (block 1): stats by lane t, applied by all.
template <int SN>
static __device__ __forceinline__ void ln_apply(u64* h2u, int hbase, u64* buf,
                                                const u64* v, u64 lg, u64 lb,
                                                int lane)
{
#pragma unroll
    for (int t = 0; t < SN; t++) buf[t * 34 + lane] = v[t];
    __syncwarp();
    if (lane < SN) {
        const float2* row = reinterpret_cast<const float2*>(&buf[lane * 34]);
        u64 s = pack2(0.f, 0.f), q = pack2(0.f, 0.f);
#pragma unroll
        for (int i = 0; i < 16; i++) {
            float4 c = *reinterpret_cast<const float4*>(&row[i * 2]);
            u64 a = pack2(c.x, c.y), b = pack2(c.z, c.w);
            s = add2(s, add2(a, b));
            q = fma2(a, a, q); q = fma2(b, b, q);
        }
        float s0, s1, q0, q1;
        unpack2(s, s0, s1); unpack2(q, q0, q1);
        float mu0 = s0 * 0.03125f, mu1 = s1 * 0.03125f;
        float r0 = rsqrtf(fmaf(-mu0, mu0, q0 * 0.03125f) + 1e-5f);
        float r1 = rsqrtf(fmaf(-mu1, mu1, q1 * 0.03125f) + 1e-5f);
        *reinterpret_cast<float4*>(&buf[LN_MU + 2 * lane]) =
            make_float4(mu0, mu1, r0, r1);
    }
    __syncwarp();
#pragma unroll
    for (int t = 0; t < SN; t++) {
        float4 ms = *reinterpret_cast<const float4*>(&buf[LN_MU + 2 * t]);
        u64 mu = pack2(ms.x, ms.y), rs = pack2(ms.z, ms.w);
        u64 t1 = mul2(rs, lg);
        h2u[hbase + t * 32 + lane] = fma2(v[t], t1, add2(lb, neg2(mul2(mu, t1))));
    }
    __syncwarp();
}

// Stage one block's weights: straight strided float4 copies (output-major).
static __device__ __forceinline__ void stage_block(float* W, const float* const* q,
                                                   int tid)
{
    for (int i4 = tid; i4 < 768; i4 += THREADS) {         // qkv [96][32]
        float4 v = reinterpret_cast<const float4*>(q[0])[i4];
        int e = i4 >> 3, c = (i4 & 7) * 4;
        *reinterpret_cast<float4*>(&W[O_QKVW + e * QKVW_STR + c]) = v;
    }
    for (int i = tid; i < 96; i += THREADS) W[O_QKVB + i] = q[1][i];
    for (int i4 = tid; i4 < 256; i4 += THREADS) {         // out_w [32][32]
        float4 v = reinterpret_cast<const float4*>(q[2])[i4];
        int e = i4 >> 3, c = (i4 & 7) * 4;
        *reinterpret_cast<float4*>(&W[O_OUTW + e * OUTW_STR + c]) = v;
    }
    if (tid < 32) {
        W[O_OUTB + tid] = q[3][tid];
        W[O_LNAG + tid] = q[4][tid];
        W[O_LNAB + tid] = q[5][tid];
    }
    for (int i4 = tid; i4 < 1024; i4 += THREADS) {        // w1 [128][32]
        float4 v = reinterpret_cast<const float4*>(q[6])[i4];
        int f = i4 >> 3, c = (i4 & 7) * 4;
        *reinterpret_cast<float4*>(&W[O_W1 + f * W1_STR + c]) = v;
    }
    for (int i = tid; i < 128; i += THREADS) W[O_B1 + i] = q[7][i];
    for (int i4 = tid; i4 < 1024; i4 += THREADS) {        // w2 [32][128]
        float4 v = reinterpret_cast<const float4*>(q[8])[i4];
        int d = i4 >> 5, c = (i4 & 31) * 4;
        *reinterpret_cast<float4*>(&W[O_W2 + d * W2_STR + c]) = v;
    }
    if (tid < 32) {
        W[O_B2   + tid] = q[9][tid];
        W[O_LNBG + tid] = q[10][tid];
        W[O_LNBB + tid] = q[11][tid];
    }
}

// FFN over tokens [SB, SB+SN) (block 1): FFN1 -> GELU -> FFN2 split-half
// -> +res -> LN_B.
template <int SB, int SN>
static __device__ __forceinline__ void ffn_pass(u64* h2u, u64* g2u,
                                                const float* W, int lane)
{
    const float2* g2f = reinterpret_cast<const float2*>(g2u);
    const float2* h2f = reinterpret_cast<const float2*>(h2u);

    // ---- FFN1: 32 -> 128 ----
    u64 ga[4][SN];
#pragma unroll
    for (int j = 0; j < 4; j++) {
        u64 b = dup2(W[O_B1 + lane + 32 * j]);
#pragma unroll
        for (int t = 0; t < SN; t++) ga[j][t] = b;
    }
    for (int d0 = 0; d0 < 32; d0 += 4) {
        u64 w[4][4];
#pragma unroll
        for (int j = 0; j < 4; j++) {
            float4 f = *reinterpret_cast<const float4*>(
                &W[O_W1 + (lane + 32 * j) * W1_STR + d0]);
            w[j][0] = dup2(f.x); w[j][1] = dup2(f.y);
            w[j][2] = dup2(f.z); w[j][3] = dup2(f.w);
        }
#pragma unroll
        for (int t = 0; t < SN; t++) {
            float4 a = *reinterpret_cast<const float4*>(&h2f[(SB + t) * 32 + d0]);
            float4 b = *reinterpret_cast<const float4*>(&h2f[(SB + t) * 32 + d0 + 2]);
            u64 x[4] = {pack2(a.x, a.y), pack2(a.z, a.w),
                        pack2(b.x, b.y), pack2(b.z, b.w)};
#pragma unroll
            for (int j = 0; j < 4; j++)
#pragma unroll
                for (int m = 0; m < 4; m++)
                    ga[j][t] = fma2(x[m], w[j][m], ga[j][t]);
        }
    }
#pragma unroll
    for (int j = 0; j < 4; j++)
#pragma unroll
        for (int t = 0; t < SN; t++) {
            float a, b; unpack2(ga[j][t], a, b);
            g2u[t * 128 + lane + 32 * j] = pack2(gelu1(a), gelu1(b));
        }
    __syncwarp();

    // ---- FFN2: 128 -> 32, split-half across lane groups ----
    const int g  = lane >> 4;
    const int lg = lane & 15;
    u64 p0[SN], p1[SN];
#pragma unroll
    for (int t = 0; t < SN; t++) { p0[t] = 0ull; p1[t] = 0ull; }
    const float*  w2a = &W[O_W2 + lg * W2_STR + g * 64];
    const float*  w2b = &W[O_W2 + (lg + 16) * W2_STR + g * 64];
    const float2* gh  = &g2f[g * 64];            // f2 offset of this f-half
    for (int fo = 0; fo < 64; fo += 4) {
        float4 wa = *reinterpret_cast<const float4*>(&w2a[fo]);
        float4 wb = *reinterpret_cast<const float4*>(&w2b[fo]);
        u64 wa0 = dup2(wa.x), wa1 = dup2(wa.y), wa2 = dup2(wa.z), wa3 = dup2(wa.w);
        u64 wb0 = dup2(wb.x), wb1 = dup2(wb.y), wb2 = dup2(wb.z), wb3 = dup2(wb.w);
#pragma unroll
        for (int t = 0; t < SN; t++) {
            float4 a = *reinterpret_cast<const float4*>(&gh[t * 128 + fo]);
            float4 b = *reinterpret_cast<const float4*>(&gh[t * 128 + fo + 2]);
            u64 x0 = pack2(a.x, a.y), x1 = pack2(a.z, a.w);
            u64 x2 = pack2(b.x, b.y), x3 = pack2(b.z, b.w);
            p0[t] = fma2(x0, wa0, p0[t]); p0[t] = fma2(x1, wa1, p0[t]);
            p0[t] = fma2(x2, wa2, p0[t]); p0[t] = fma2(x3, wa3, p0[t]);
            p1[t] = fma2(x0, wb0, p1[t]); p1[t] = fma2(x1, wb1, p1[t]);
            p1[t] = fma2(x2, wb2, p1[t]); p1[t] = fma2(x3, wb3, p1[t]);
        }
    }
    u64 o2[SN];
    {
        u64 bias = dup2(W[O_B2 + lane]);
#pragma unroll
        for (int t = 0; t < SN; t++) {
            u64 r0 = add2(p0[t], shflx2(p0[t], 16));
            u64 r1 = add2(p1[t], shflx2(p1[t], 16));
            o2[t] = add2(add2((lane < 16) ? r0 : r1, bias),
                         h2u[(SB + t) * 32 + lane]);
        }
    }
    __syncwarp();
    ln_apply<SN>(h2u, SB * 32, g2u,
                 o2, dup2(W[O_LNBG + lane]), dup2(W[O_LNBB + lane]), lane);
}

// Block 1: full transformer block for a packed batch-pair.
__device__ __noinline__ void block_pair(int hoff, int soff, int lane)
{
    u64* h2u = reinterpret_cast<u64*>(&smem[hoff]);
    u64* stg = reinterpret_cast<u64*>(&smem[soff]);
    const float2* h2f = reinterpret_cast<const float2*>(h2u);
    const float2* stf = reinterpret_cast<const float2*>(stg);
    const float* W = &smem[O_BLKW];

    // ---------------- QKV projection (lane = output dim) ----------------
    u64 qa[S], ka[S], va[S];
    {
        u64 bq = dup2(W[O_QKVB + lane]);
        u64 bk = dup2(W[O_QKVB + 32 + lane]);
        u64 bv = dup2(W[O_QKVB + 64 + lane]);
#pragma unroll
        for (int s = 0; s < S; s++) { qa[s] = bq; ka[s] = bk; va[s] = bv; }
    }
    for (int d0 = 0; d0 < 32; d0 += 4) {
        float4 fq = *reinterpret_cast<const float4*>(&W[O_QKVW + lane * QKVW_STR + d0]);
        float4 fk = *reinterpret_cast<const float4*>(&W[O_QKVW + (lane + 32) * QKVW_STR + d0]);
        float4 fv = *reinterpret_cast<const float4*>(&W[O_QKVW + (lane + 64) * QKVW_STR + d0]);
        u64 wq[4] = {dup2(fq.x), dup2(fq.y), dup2(fq.z), dup2(fq.w)};
        u64 wk[4] = {dup2(fk.x), dup2(fk.y), dup2(fk.z), dup2(fk.w)};
        u64 wv[4] = {dup2(fv.x), dup2(fv.y), dup2(fv.z), dup2(fv.w)};
#pragma unroll
        for (int s = 0; s < S; s++) {
            float4 a = *reinterpret_cast<const float4*>(&h2f[s * 32 + d0]);
            float4 b = *reinterpret_cast<const float4*>(&h2f[s * 32 + d0 + 2]);
            u64 x[4] = {pack2(a.x, a.y), pack2(a.z, a.w),
                        pack2(b.x, b.y), pack2(b.z, b.w)};
#pragma unroll
            for (int j = 0; j < 4; j++) {
                qa[s] = fma2(x[j], wq[j], qa[s]);
                ka[s] = fma2(x[j], wk[j], ka[s]);
                va[s] = fma2(x[j], wv[j], va[s]);
            }
        }
    }
    {
        u64 scl = dup2(0.35355339059327373f);
#pragma unroll
        for (int s = 0; s < S; s++) qa[s] = mul2(qa[s], scl);
    }

    // ---------------- attention: two head-pair passes, shuffle-free ---------
    const int qi = (lane >> 1) > 10 ? 10 : (lane >> 1);
    const int hl = lane & 1;
    const int hb = hl * 8;
#pragma unroll
    for (int p = 0; p < 2; p++) {
        if ((lane >> 4) == p) {
            int ld = lane & 15;
#pragma unroll
            for (int s = 0; s < S; s++) {
                stg[F2_QS + s * 16 + ld] = qa[s];
                stg[F2_KS + s * 16 + ld] = ka[s];
                stg[F2_VS + s * 16 + ld] = va[s];
            }
        }
        __syncwarp();

        u64 qr[8];
#pragma unroll
        for (int j = 0; j < 8; j += 2) {
            float4 t = *reinterpret_cast<const float4*>(&stf[F2_QS + qi * 16 + hb + j]);
            qr[j] = pack2(t.x, t.y); qr[j + 1] = pack2(t.z, t.w);
        }
        float e0[S], e1[S];
#pragma unroll
        for (int ki = 0; ki < S; ki++) {
            u64 acc = pack2(0.f, 0.f);
#pragma unroll
            for (int j = 0; j < 8; j += 2) {
                float4 kv = *reinterpret_cast<const float4*>(&stf[F2_KS + ki * 16 + hb + j]);
                acc = fma2(qr[j],     pack2(kv.x, kv.y), acc);
                acc = fma2(qr[j + 1], pack2(kv.z, kv.w), acc);
            }
            unpack2(acc, e0[ki], e1[ki]);
        }
        float m0 = e0[0], m1 = e1[0];
#pragma unroll
        for (int ki = 1; ki < S; ki++) { m0 = fmaxf(m0, e0[ki]); m1 = fmaxf(m1, e1[ki]); }
        float den0 = 0.f, den1 = 0.f;
#pragma unroll
        for (int ki = 0; ki < S; ki++) {
            e0[ki] = __expf(e0[ki] - m0); den0 += e0[ki];
            e1[ki] = __expf(e1[ki] - m1); den1 += e1[ki];
        }
        u64 cacc[8];
#pragma unroll
        for (int j = 0; j < 8; j++) cacc[j] = pack2(0.f, 0.f);
#pragma unroll
        for (int ki = 0; ki < S; ki++) {
            u64 ev = pack2(e0[ki], e1[ki]);
#pragma unroll
            for (int j = 0; j < 8; j += 2) {
                float4 vv = *reinterpret_cast<const float4*>(&stf[F2_VS + ki * 16 + hb + j]);
                cacc[j]     = fma2(ev, pack2(vv.x, vv.y), cacc[j]);
                cacc[j + 1] = fma2(ev, pack2(vv.z, vv.w), cacc[j + 1]);
            }
        }
        if (lane < 22) {
            u64 inv = pack2(1.0f / den0, 1.0f / den1);
            int cb = F2_CTX + qi * CTX_STR + (p * 2 + hl) * 8;
#pragma unroll
            for (int j = 0; j < 8; j++) stg[cb + j] = mul2(cacc[j], inv);
        }
        __syncwarp();
    }

    // ------------- output projection (split-half) + residual + LN_A ---------
    {
        const int g  = lane >> 4;
        const int lg = lane & 15;
        u64 po0[S], po1[S];
#pragma unroll
        for (int s = 0; s < S; s++) { po0[s] = 0ull; po1[s] = 0ull; }
        const float* owa = &W[O_OUTW + lg * OUTW_STR + g * 16];
        const float* owb = &W[O_OUTW + (lg + 16) * OUTW_STR + g * 16];
        for (int dd = 0; dd < 16; dd += 4) {
            float4 wa = *reinterpret_cast<const float4*>(&owa[dd]);
            float4 wb = *reinterpret_cast<const float4*>(&owb[dd]);
            u64 wa0 = dup2(wa.x), wa1 = dup2(wa.y), wa2 = dup2(wa.z), wa3 = dup2(wa.w);
            u64 wb0 = dup2(wb.x), wb1 = dup2(wb.y), wb2 = dup2(wb.z), wb3 = dup2(wb.w);
#pragma unroll
            for (int s = 0; s < S; s++) {
                float4 c0 = *reinterpret_cast<const float4*>(
                    &stf[F2_CTX + s * CTX_STR + g * 16 + dd]);
                float4 c1 = *reinterpret_cast<const float4*>(
                    &stf[F2_CTX + s * CTX_STR + g * 16 + dd + 2]);
                u64 x0 = pack2(c0.x, c0.y), x1 = pack2(c0.z, c0.w);
                u64 x2 = pack2(c1.x, c1.y), x3 = pack2(c1.z, c1.w);
                po0[s] = fma2(x0, wa0, po0[s]); po0[s] = fma2(x1, wa1, po0[s]);
                po0[s] = fma2(x2, wa2, po0[s]); po0[s] = fma2(x3, wa3, po0[s]);
                po1[s] = fma2(x0, wb0, po1[s]); po1[s] = fma2(x1, wb1, po1[s]);
                po1[s] = fma2(x2, wb2, po1[s]); po1[s] = fma2(x3, wb3, po1[s]);
            }
        }
        u64 bo = dup2(W[O_OUTB + lane]);
        u64 o[S];
#pragma unroll
        for (int s = 0; s < S; s++) {
            u64 r0 = add2(po0[s], shflx2(po0[s], 16));
            u64 r1 = add2(po1[s], shflx2(po1[s], 16));
            o[s] = add2(add2((lane < 16) ? r0 : r1, bo), h2u[s * 32 + lane]);
        }
        __syncwarp();
        ln_apply<S>(h2u, 0, stg + F2_CTX,
                    o, dup2(W[O_LNAG + lane]), dup2(W[O_LNAB + lane]), lane);
    }

    ffn_pass<0, 6>(h2u, stg, W, lane);
    ffn_pass<6, 5>(h2u, stg, W, lane);
}

// Block 2: CLS-specialized — K/V for all tokens; V stays in registers.
__device__ __noinline__ void block2_pair(int hoff, int soff, int lane)
{
    u64* h2u = reinterpret_cast<u64*>(&smem[hoff]);
    u64* stg = reinterpret_cast<u64*>(&smem[soff]);
    const float2* h2f = reinterpret_cast<const float2*>(h2u);
    const float2* stf = reinterpret_cast<const float2*>(stg);
    const float* W = &smem[O_BLKW];

    // ---------------- QKV: k,v all tokens; q token 0 only -------------------
    u64 ka[S], va[S];
    u64 q0 = dup2(W[O_QKVB + lane]);
    {
        u64 bk = dup2(W[O_QKVB + 32 + lane]);
        u64 bv = dup2(W[O_QKVB + 64 + lane]);
#pragma unroll
        for (int s = 0; s < S; s++) { ka[s] = bk; va[s] = bv; }
    }
    for (int d0 = 0; d0 < 32; d0 += 4) {
        float4 fq = *reinterpret_cast<const float4*>(&W[O_QKVW + lane * QKVW_STR + d0]);
        float4 fk = *reinterpret_cast<const float4*>(&W[O_QKVW + (lane + 32) * QKVW_STR + d0]);
        float4 fv = *reinterpret_cast<const float4*>(&W[O_QKVW + (lane + 64) * QKVW_STR + d0]);
        u64 wq[4] = {dup2(fq.x), dup2(fq.y), dup2(fq.z), dup2(fq.w)};
        u64 wk[4] = {dup2(fk.x), dup2(fk.y), dup2(fk.z), dup2(fk.w)};
        u64 wv[4] = {dup2(fv.x), dup2(fv.y), dup2(fv.z), dup2(fv.w)};
#pragma unroll
        for (int s = 0; s < S; s++) {
            float4 a = *reinterpret_cast<const float4*>(&h2f[s * 32 + d0]);
            float4 b = *reinterpret_cast<const float4*>(&h2f[s * 32 + d0 + 2]);
            u64 x[4] = {pack2(a.x, a.y), pack2(a.z, a.w),
                        pack2(b.x, b.y), pack2(b.z, b.w)};
#pragma unroll
            for (int j = 0; j < 4; j++) {
                ka[s] = fma2(x[j], wk[j], ka[s]);
                va[s] = fma2(x[j], wv[j], va[s]);
            }
            if (s == 0) {
#pragma unroll
                for (int j = 0; j < 4; j++) q0 = fma2(x[j], wq[j], q0);
            }
        }
    }
    q0 = mul2(q0, dup2(0.35355339059327373f));

    // stage q0 / K only (lane = dim); V stays in registers
    stg[F2_Q2 + lane] = q0;
#pragma unroll
    for (int s = 0; s < S; s++)
        stg[F2_K2 + s * 32 + lane] = ka[s];
    __syncwarp();

    // ---------------- attention row 0: lane = dim, head = lane>>3 -----------
    const int hb2 = (lane >> 3) * 8;
    u64 qr[8];
#pragma unroll
    for (int j = 0; j < 8; j += 2) {
        float4 t = *reinterpret_cast<const float4*>(&stf[F2_Q2 + hb2 + j]);
        qr[j] = pack2(t.x, t.y); qr[j + 1] = pack2(t.z, t.w);
    }
    float e0[S], e1[S];
#pragma unroll
    for (int ki = 0; ki < S; ki++) {
        u64 acc = pack2(0.f, 0.f);
#pragma unroll
        for (int j = 0; j < 8; j += 2) {
            float4 kv = *reinterpret_cast<const float4*>(&stf[F2_K2 + ki * 32 + hb2 + j]);
            acc = fma2(qr[j],     pack2(kv.x, kv.y), acc);
            acc = fma2(qr[j + 1], pack2(kv.z, kv.w), acc);
        }
        unpack2(acc, e0[ki], e1[ki]);
    }
    float m0 = e0[0], m1 = e1[0];
#pragma unroll
    for (int ki = 1; ki < S; ki++) { m0 = fmaxf(m0, e0[ki]); m1 = fmaxf(m1, e1[ki]); }
    float den0 = 0.f, den1 = 0.f;
#pragma unroll
    for (int ki = 0; ki < S; ki++) {
        e0[ki] = __expf(e0[ki] - m0); den0 += e0[ki];
        e1[ki] = __expf(e1[ki] - m1); den1 += e1[ki];
    }
    u64 c = pack2(0.f, 0.f);
#pragma unroll
    for (int ki = 0; ki < S; ki++)
        c = fma2(pack2(e0[ki], e1[ki]), va[ki], c);    // V from registers
    c = mul2(c, pack2(1.0f / den0, 1.0f / den1));
    stg[F2_C2 + lane] = c;
    __syncwarp();

    // ------------- out-proj token 0 (split-half) + residual + LN_A ----------
    u64 hn;
    {
        const int g  = lane >> 4;
        const int lg = lane & 15;
        u64 p0 = 0ull, p1 = 0ull;
        const float* owa = &W[O_OUTW + lg * OUTW_STR + g * 16];
        const float* owb = &W[O_OUTW + (lg + 16) * OUTW_STR + g * 16];
        for (int dd = 0; dd < 16; dd += 4) {
            float4 wa = *reinterpret_cast<const float4*>(&owa[dd]);
            float4 wb = *reinterpret_cast<const float4*>(&owb[dd]);
            float4 c0 = *reinterpret_cast<const float4*>(&stf[F2_C2 + g * 16 + dd]);
            float4 c1 = *reinterpret_cast<const float4*>(&stf[F2_C2 + g * 16 + dd + 2]);
            u64 x0 = pack2(c0.x, c0.y), x1 = pack2(c0.z, c0.w);
            u64 x2 = pack2(c1.x, c1.y), x3 = pack2(c1.z, c1.w);
            p0 = fma2(x0, dup2(wa.x), p0); p0 = fma2(x1, dup2(wa.y), p0);
            p0 = fma2(x2, dup2(wa.z), p0); p0 = fma2(x3, dup2(wa.w), p0);
            p1 = fma2(x0, dup2(wb.x), p1); p1 = fma2(x1, dup2(wb.y), p1);
            p1 = fma2(x2, dup2(wb.z), p1); p1 = fma2(x3, dup2(wb.w), p1);
        }
        u64 r0 = add2(p0, shflx2(p0, 16));
        u64 r1 = add2(p1, shflx2(p1, 16));
        u64 o = add2(add2((lane < 16) ? r0 : r1, dup2(W[O_OUTB + lane])),
                     h2u[lane]);
        hn = ln_norm(o, dup2(W[O_LNAG + lane]), dup2(W[O_LNAB + lane]));
        h2u[lane] = hn;
    }
    __syncwarp();

    // ---------------- FFN token 0 -------------------------------------------
    u64 ga[4];
#pragma unroll
    for (int j = 0; j < 4; j++) ga[j] = dup2(W[O_B1 + lane + 32 * j]);
    for (int d0 = 0; d0 < 32; d0 += 4) {
        float4 a = *reinterpret_cast<const float4*>(&h2f[d0]);
        float4 b = *reinterpret_cast<const float4*>(&h2f[d0 + 2]);
        u64 x[4] = {pack2(a.x, a.y), pack2(a.z, a.w),
                    pack2(b.x, b.y), pack2(b.z, b.w)};
#pragma unroll
        for (int j = 0; j < 4; j++) {
            float4 f = *reinterpret_cast<const float4*>(
                &W[O_W1 + (lane + 32 * j) * W1_STR + d0]);
            ga[j] = fma2(x[0], dup2(f.x), ga[j]);
            ga[j] = fma2(x[1], dup2(f.y), ga[j]);
            ga[j] = fma2(x[2], dup2(f.z), ga[j]);
            ga[j] = fma2(x[3], dup2(f.w), ga[j]);
        }
    }
#pragma unroll
    for (int j = 0; j < 4; j++) {
        float a, b; unpack2(ga[j], a, b);
        stg[F2_G2 + lane + 32 * j] = pack2(gelu1(a), gelu1(b));
    }
    __syncwarp();

    // ---- FFN2 token 0, split-half ----
    {
        const int g  = lane >> 4;
        const int lg = lane & 15;
        u64 p0 = 0ull, p1 = 0ull;
        const float*  w2a = &W[O_W2 + lg * W2_STR + g * 64];
        const float*  w2b = &W[O_W2 + (lg + 16) * W2_STR + g * 64];
        const float2* gh  = &stf[F2_G2 + g * 64];
        for (int fo = 0; fo < 64; fo += 4) {
            float4 wa = *reinterpret_cast<const float4*>(&w2a[fo]);
            float4 wb = *reinterpret_cast<const float4*>(&w2b[fo]);
            float4 a = *reinterpret_cast<const float4*>(&gh[fo]);
            float4 b = *reinterpret_cast<const float4*>(&gh[fo + 2]);
            u64 x0 = pack2(a.x, a.y), x1 = pack2(a.z, a.w);
            u64 x2 = pack2(b.x, b.y), x3 = pack2(b.z, b.w);
            p0 = fma2(x0, dup2(wa.x), p0); p0 = fma2(x1, dup2(wa.y), p0);
            p0 = fma2(x2, dup2(wa.z), p0); p0 = fma2(x3, dup2(wa.w), p0);
            p1 = fma2(x0, dup2(wb.x), p1); p1 = fma2(x1, dup2(wb.y), p1);
            p1 = fma2(x2, dup2(wb.z), p1); p1 = fma2(x3, dup2(wb.w), p1);
        }
        u64 r0 = add2(p0, shflx2(p0, 16));
        u64 r1 = add2(p1, shflx2(p1, 16));
        u64 o2 = add2(add2((lane < 16) ? r0 : r1, dup2(W[O_B2 + lane])), hn);
        h2u[lane] = ln_norm(o2, dup2(W[O_LNBG + lane]), dup2(W[O_LNBB + lane]));
    }
    __syncwarp();
}

__global__ void __launch_bounds__(THREADS)
tab_transformer_kernel(KParams p)
{
    const int tid = threadIdx.x;

    for (int i = tid; i < 320; i += THREADS) smem[O_WFEAT + i] = p.in[1][i];
    for (int i = tid; i < 320; i += THREADS) smem[O_BFEAT + i] = p.in[2][i];
    if (tid < 32) {
        smem[O_CLS  + tid] = p.in[3][tid];
        smem[O_CLFW + tid] = p.in[28][tid];
    }
    if (tid == 0) smem[O_CLFB] = p.in[29][0];
    stage_block(&smem[O_BLKW], &p.in[4], tid);
    __syncthreads();

    const int warp = tid >> 5, lane = tid & 31;
    int pr = blockIdx.x * NW + warp;
    const bool valid = (pr < NPAIR);
    if (!valid) pr = NPAIR - 1;
    const int b0 = pr * 2;

    const int hoff = O_ACT + warp * ACT_F;
    const int soff = hoff + H2_F;
    u64* h2u = reinterpret_cast<u64*>(&smem[hoff]);

    float xv0 = (lane < 10) ? p.in[0][(size_t)b0 * 10 + lane] : 0.f;
    float xv1 = (lane < 10) ? p.in[0][(size_t)(b0 + 1) * 10 + lane] : 0.f;
    h2u[lane] = dup2(smem[O_CLS + lane]);
#pragma unroll
    for (int i = 0; i < 10; i++) {
        float a = __shfl_sync(0xffffffffu, xv0, i);
        float b = __shfl_sync(0xffffffffu, xv1, i);
        u64 w  = dup2(smem[O_WFEAT + i * 32 + lane]);
        u64 bb = dup2(smem[O_BFEAT + i * 32 + lane]);
        h2u[(i + 1) * 32 + lane] = fma2(pack2(a, b), w, bb);
    }
    __syncwarp();

    block_pair(hoff, soff, lane);

    __syncthreads();
    stage_block(&smem[O_BLKW], &p.in[16], tid);
    __syncthreads();

    block2_pair(hoff, soff, lane);

    u64 v = mul2(h2u[lane], dup2(smem[O_CLFW + lane]));
#pragma unroll
    for (int mk = 16; mk; mk >>= 1) v = add2(v, shflx2(v, mk));
    if (valid && lane == 0) {
        float r0, r1; unpack2(v, r0, r1);
        float cb = smem[O_CLFB];
        *reinterpret_cast<float2*>(&p.out[b0]) = make_float2(r0 + cb, r1 + cb);
    }
}

extern "C" void kernel_launch(void* const* d_in, const int* in_sizes, int n_in,
                              void* d_out, int out_size)
{
    (void)in_sizes; (void)n_in; (void)out_size;
    KParams p;
    for (int i = 0; i < 30; i++) p.in[i] = (const float*)d_in[i];
    p.out = (float*)d_out;

    cudaFuncSetAttribute(tab_transformer_kernel,
                         cudaFuncAttributeMaxDynamicSharedMemorySize, SMEM_BYTES);

    const int grid = (NPAIR + NW - 1) / NW;   // 4096
    tab_transformer_kernel<<<grid, THREADS, SMEM_BYTES>>>(p);
}

// round 13
// speedup vs baseline: 1.5984x; 1.5984x over previous
#include <cuda_runtime.h>

// Fused 2-block tiny-transformer, 131072 sequences. One warp = TWO batches
// packed as f32x2. Block 1: full 11-token block; FFN2 split-half (SN<=6
// partial arrays — fits registers); out-proj UNSPLIT (S=11 partials spill).
// Block 2: CLS-specialized; V in registers; out-proj + FFN2 split-half with
// scalar partials.

namespace {
constexpr int S  = 11;
constexpr int NW = 16;
constexpr int THREADS = NW * 32;                  // 512
constexpr int BTOT = 131072;
constexpr int NPAIR = BTOT / 2;                   // 65536

// --- per-block weight layout (floats), output-major rows, stride%32==4 ------
constexpr int QKVW_STR = 36;
constexpr int OUTW_STR = 36;
constexpr int W1_STR   = 36;
constexpr int W2_STR   = 132;

constexpr int O_QKVW = 0;
constexpr int O_QKVB = O_QKVW + 96 * QKVW_STR;    // 3456
constexpr int O_OUTW = O_QKVB + 96;               // 3552
constexpr int O_OUTB = O_OUTW + 32 * OUTW_STR;    // 4704
constexpr int O_LNAG = O_OUTB + 32;
constexpr int O_LNAB = O_LNAG + 32;
constexpr int O_W1   = O_LNAB + 32;               // 4800
constexpr int O_B1   = O_W1 + 128 * W1_STR;       // 9408
constexpr int O_W2   = O_B1 + 128;                // 9536
constexpr int O_B2   = O_W2 + 32 * W2_STR;        // 13760
constexpr int O_LNBG = O_B2 + 32;
constexpr int O_LNBB = O_LNBG + 32;
constexpr int BLK_SZ = O_LNBB + 32;               // 13856

// --- global smem layout (floats) ---
constexpr int O_WFEAT = 0;
constexpr int O_BFEAT = O_WFEAT + 320;
constexpr int O_CLS   = O_BFEAT + 320;
constexpr int O_CLFW  = O_CLS + 32;
constexpr int O_CLFB  = O_CLFW + 32;
constexpr int O_BLKW  = 720;
constexpr int O_ACT   = O_BLKW + BLK_SZ;          // 14576

// per-warp activation region (floats)
constexpr int H2_F   = 12 * 32 * 2;               // h2 [12][32] float2 = 768
// block1 staging (float2 units): q[11][16], k[11][16], v[11][16], ctx[11][34]
constexpr int F2_QS  = 0;
constexpr int F2_KS  = 176;
constexpr int F2_VS  = 352;
constexpr int F2_CTX = 528;
constexpr int CTX_STR = 34;
constexpr int LN_MU  = 374;                       // mu/sig offset in LN buf
// block2 staging (float2 units): q0[32], k[11][32], ctx[32]
constexpr int F2_Q2  = 0;
constexpr int F2_K2  = 32;
constexpr int F2_C2  = 736;
constexpr int F2_G2  = 0;                         // ffn g buffer (reuse)
constexpr int STG_F2 = 928;
constexpr int ACT_F  = H2_F + STG_F2 * 2;         // 2624 floats / warp
constexpr int SMEM_FLOATS = O_ACT + NW * ACT_F;   // 56560
constexpr int SMEM_BYTES  = SMEM_FLOATS * 4;      // 226240
}

extern __shared__ float smem[];

using u64 = unsigned long long;

static __device__ __forceinline__ u64 pack2(float x, float y) {
    u64 r; asm("mov.b64 %0,{%1,%2};" : "=l"(r) : "f"(x), "f"(y)); return r;
}
static __device__ __forceinline__ void unpack2(u64 v, float& x, float& y) {
    asm("mov.b64 {%0,%1},%2;" : "=f"(x), "=f"(y) : "l"(v));
}
static __device__ __forceinline__ u64 dup2(float x) { return pack2(x, x); }
static __device__ __forceinline__ u64 fma2(u64 a, u64 b, u64 c) {
    u64 d; asm("fma.rn.f32x2 %0,%1,%2,%3;" : "=l"(d) : "l"(a), "l"(b), "l"(c)); return d;
}
static __device__ __forceinline__ u64 add2(u64 a, u64 b) {
    u64 d; asm("add.rn.f32x2 %0,%1,%2;" : "=l"(d) : "l"(a), "l"(b)); return d;
}
static __device__ __forceinline__ u64 mul2(u64 a, u64 b) {
    u64 d; asm("mul.rn.f32x2 %0,%1,%2;" : "=l"(d) : "l"(a), "l"(b)); return d;
}
static __device__ __forceinline__ u64 neg2(u64 x) {
    return x ^ 0x8000000080000000ULL;
}
static __device__ __forceinline__ u64 shflx2(u64 v, int m) {
    float x, y; unpack2(v, x, y);
    x = __shfl_xor_sync(0xffffffffu, x, m);
    y = __shfl_xor_sync(0xffffffffu, y, m);
    return pack2(x, y);
}
static __device__ __forceinline__ float gelu1(float x) {
    return 0.5f * x * (1.0f + erff(x * 0.7071067811865475f));
}
// single-token LN via butterfly (block 2)
static __device__ __forceinline__ u64 ln_norm(u64 v, u64 lg, u64 lb) {
    u64 sum = v, sq = mul2(v, v);
#pragma unroll
    for (int mk = 16; mk; mk >>= 1) {
        sum = add2(sum, shflx2(sum, mk));
        sq  = add2(sq,  shflx2(sq,  mk));
    }
    float s0, s1, q0, q1, v0, v1;
    unpack2(sum, s0, s1); unpack2(sq, q0, q1); unpack2(v, v0, v1);
    float mu0 = s0 * 0.03125f, mu1 = s1 * 0.03125f;
    float r0 = rsqrtf(fmaf(-mu0, mu0, q0 * 0.03125f) + 1e-5f);
    float r1 = rsqrtf(fmaf(-mu1, mu1, q1 * 0.03125f) + 1e-5f);
    return fma2(pack2((v0 - mu0) * r0, (v1 - mu1) * r1), lg, lb);
}

struct KParams {
    const float* in[30];
    float* out;
};

// Staged LayerNorm over SN tokens (block 1): stats by lane t, applied by all.
template <int SN>
static __device__ __forceinline__ void ln_apply(u64* h2u, int hbase, u64* buf,
                                                const u64* v, u64 lg, u64 lb,
                                                int lane)
{
#pragma unroll
    for (int t = 0; t < SN; t++) buf[t * 34 + lane] = v[t];
    __syncwarp();
    if (lane < SN) {
        const float2* row = reinterpret_cast<const float2*>(&buf[lane * 34]);
        u64 s = pack2(0.f, 0.f), q = pack2(0.f, 0.f);
#pragma unroll
        for (int i = 0; i < 16; i++) {
            float4 c = *reinterpret_cast<const float4*>(&row[i * 2]);
            u64 a = pack2(c.x, c.y), b = pack2(c.z, c.w);
            s = add2(s, add2(a, b));
            q = fma2(a, a, q); q = fma2(b, b, q);
        }
        float s0, s1, q0, q1;
        unpack2(s, s0, s1); unpack2(q, q0, q1);
        float mu0 = s0 * 0.03125f, mu1 = s1 * 0.03125f;
        float r0 = rsqrtf(fmaf(-mu0, mu0, q0 * 0.03125f) + 1e-5f);
        float r1 = rsqrtf(fmaf(-mu1, mu1, q1 * 0.03125f) + 1e-5f);
        *reinterpret_cast<float4*>(&buf[LN_MU + 2 * lane]) =
            make_float4(mu0, mu1, r0, r1);
    }
    __syncwarp();
#pragma unroll
    for (int t = 0; t < SN; t++) {
        float4 ms = *reinterpret_cast<const float4*>(&buf[LN_MU + 2 * t]);
        u64 mu = pack2(ms.x, ms.y), rs = pack2(ms.z, ms.w);
        u64 t1 = mul2(rs, lg);
        h2u[hbase + t * 32 + lane] = fma2(v[t], t1, add2(lb, neg2(mul2(mu, t1))));
    }
    __syncwarp();
}

// Stage one block's weights: straight strided float4 copies (output-major).
static __device__ __forceinline__ void stage_block(float* W, const float* const* q,
                                                   int tid)
{
    for (int i4 = tid; i4 < 768; i4 += THREADS) {         // qkv [96][32]
        float4 v = reinterpret_cast<const float4*>(q[0])[i4];
        int e = i4 >> 3, c = (i4 & 7) * 4;
        *reinterpret_cast<float4*>(&W[O_QKVW + e * QKVW_STR + c]) = v;
    }
    for (int i = tid; i < 96; i += THREADS) W[O_QKVB + i] = q[1][i];
    for (int i4 = tid; i4 < 256; i4 += THREADS) {         // out_w [32][32]
        float4 v = reinterpret_cast<const float4*>(q[2])[i4];
        int e = i4 >> 3, c = (i4 & 7) * 4;
        *reinterpret_cast<float4*>(&W[O_OUTW + e * OUTW_STR + c]) = v;
    }
    if (tid < 32) {
        W[O_OUTB + tid] = q[3][tid];
        W[O_LNAG + tid] = q[4][tid];
        W[O_LNAB + tid] = q[5][tid];
    }
    for (int i4 = tid; i4 < 1024; i4 += THREADS) {        // w1 [128][32]
        float4 v = reinterpret_cast<const float4*>(q[6])[i4];
        int f = i4 >> 3, c = (i4 & 7) * 4;
        *reinterpret_cast<float4*>(&W[O_W1 + f * W1_STR + c]) = v;
    }
    for (int i = tid; i < 128; i += THREADS) W[O_B1 + i] = q[7][i];
    for (int i4 = tid; i4 < 1024; i4 += THREADS) {        // w2 [32][128]
        float4 v = reinterpret_cast<const float4*>(q[8])[i4];
        int d = i4 >> 5, c = (i4 & 31) * 4;
        *reinterpret_cast<float4*>(&W[O_W2 + d * W2_STR + c]) = v;
    }
    if (tid < 32) {
        W[O_B2   + tid] = q[9][tid];
        W[O_LNBG + tid] = q[10][tid];
        W[O_LNBB + tid] = q[11][tid];
    }
}

// FFN over tokens [SB, SB+SN) (block 1): FFN1 -> GELU -> FFN2 split-half
// -> +res -> LN_B.
template <int SB, int SN>
static __device__ __forceinline__ void ffn_pass(u64* h2u, u64* g2u,
                                                const float* W, int lane)
{
    const float2* g2f = reinterpret_cast<const float2*>(g2u);
    const float2* h2f = reinterpret_cast<const float2*>(h2u);

    // ---- FFN1: 32 -> 128 ----
    u64 ga[4][SN];
#pragma unroll
    for (int j = 0; j < 4; j++) {
        u64 b = dup2(W[O_B1 + lane + 32 * j]);
#pragma unroll
        for (int t = 0; t < SN; t++) ga[j][t] = b;
    }
    for (int d0 = 0; d0 < 32; d0 += 4) {
        u64 w[4][4];
#pragma unroll
        for (int j = 0; j < 4; j++) {
            float4 f = *reinterpret_cast<const float4*>(
                &W[O_W1 + (lane + 32 * j) * W1_STR + d0]);
            w[j][0] = dup2(f.x); w[j][1] = dup2(f.y);
            w[j][2] = dup2(f.z); w[j][3] = dup2(f.w);
        }
#pragma unroll
        for (int t = 0; t < SN; t++) {
            float4 a = *reinterpret_cast<const float4*>(&h2f[(SB + t) * 32 + d0]);
            float4 b = *reinterpret_cast<const float4*>(&h2f[(SB + t) * 32 + d0 + 2]);
            u64 x[4] = {pack2(a.x, a.y), pack2(a.z, a.w),
                        pack2(b.x, b.y), pack2(b.z, b.w)};
#pragma unroll
            for (int j = 0; j < 4; j++)
#pragma unroll
                for (int m = 0; m < 4; m++)
                    ga[j][t] = fma2(x[m], w[j][m], ga[j][t]);
        }
    }
#pragma unroll
    for (int j = 0; j < 4; j++)
#pragma unroll
        for (int t = 0; t < SN; t++) {
            float a, b; unpack2(ga[j][t], a, b);
            g2u[t * 128 + lane + 32 * j] = pack2(gelu1(a), gelu1(b));
        }
    __syncwarp();

    // ---- FFN2: 128 -> 32, split-half across lane groups ----
    const int g  = lane >> 4;
    const int lg = lane & 15;
    u64 p0[SN], p1[SN];
#pragma unroll
    for (int t = 0; t < SN; t++) { p0[t] = 0ull; p1[t] = 0ull; }
    const float*  w2a = &W[O_W2 + lg * W2_STR + g * 64];
    const float*  w2b = &W[O_W2 + (lg + 16) * W2_STR + g * 64];
    const float2* gh  = &g2f[g * 64];            // f2 offset of this f-half
    for (int fo = 0; fo < 64; fo += 4) {
        float4 wa = *reinterpret_cast<const float4*>(&w2a[fo]);
        float4 wb = *reinterpret_cast<const float4*>(&w2b[fo]);
        u64 wa0 = dup2(wa.x), wa1 = dup2(wa.y), wa2 = dup2(wa.z), wa3 = dup2(wa.w);
        u64 wb0 = dup2(wb.x), wb1 = dup2(wb.y), wb2 = dup2(wb.z), wb3 = dup2(wb.w);
#pragma unroll
        for (int t = 0; t < SN; t++) {
            float4 a = *reinterpret_cast<const float4*>(&gh[t * 128 + fo]);
            float4 b = *reinterpret_cast<const float4*>(&gh[t * 128 + fo + 2]);
            u64 x0 = pack2(a.x, a.y), x1 = pack2(a.z, a.w);
            u64 x2 = pack2(b.x, b.y), x3 = pack2(b.z, b.w);
            p0[t] = fma2(x0, wa0, p0[t]); p0[t] = fma2(x1, wa1, p0[t]);
            p0[t] = fma2(x2, wa2, p0[t]); p0[t] = fma2(x3, wa3, p0[t]);
            p1[t] = fma2(x0, wb0, p1[t]); p1[t] = fma2(x1, wb1, p1[t]);
            p1[t] = fma2(x2, wb2, p1[t]); p1[t] = fma2(x3, wb3, p1[t]);
        }
    }
    u64 o2[SN];
    {
        u64 bias = dup2(W[O_B2 + lane]);
#pragma unroll
        for (int t = 0; t < SN; t++) {
            u64 r0 = add2(p0[t], shflx2(p0[t], 16));
            u64 r1 = add2(p1[t], shflx2(p1[t], 16));
            o2[t] = add2(add2((lane < 16) ? r0 : r1, bias),
                         h2u[(SB + t) * 32 + lane]);
        }
    }
    __syncwarp();
    ln_apply<SN>(h2u, SB * 32, g2u,
                 o2, dup2(W[O_LNBG + lane]), dup2(W[O_LNBB + lane]), lane);
}

// Block 1: full transformer block for a packed batch-pair.
__device__ __noinline__ void block_pair(int hoff, int soff, int lane)
{
    u64* h2u = reinterpret_cast<u64*>(&smem[hoff]);
    u64* stg = reinterpret_cast<u64*>(&smem[soff]);
    const float2* h2f = reinterpret_cast<const float2*>(h2u);
    const float2* stf = reinterpret_cast<const float2*>(stg);
    const float* W = &smem[O_BLKW];

    // ---------------- QKV projection (lane = output dim) ----------------
    u64 qa[S], ka[S], va[S];
    {
        u64 bq = dup2(W[O_QKVB + lane]);
        u64 bk = dup2(W[O_QKVB + 32 + lane]);
        u64 bv = dup2(W[O_QKVB + 64 + lane]);
#pragma unroll
        for (int s = 0; s < S; s++) { qa[s] = bq; ka[s] = bk; va[s] = bv; }
    }
    for (int d0 = 0; d0 < 32; d0 += 4) {
        float4 fq = *reinterpret_cast<const float4*>(&W[O_QKVW + lane * QKVW_STR + d0]);
        float4 fk = *reinterpret_cast<const float4*>(&W[O_QKVW + (lane + 32) * QKVW_STR + d0]);
        float4 fv = *reinterpret_cast<const float4*>(&W[O_QKVW + (lane + 64) * QKVW_STR + d0]);
        u64 wq[4] = {dup2(fq.x), dup2(fq.y), dup2(fq.z), dup2(fq.w)};
        u64 wk[4] = {dup2(fk.x), dup2(fk.y), dup2(fk.z), dup2(fk.w)};
        u64 wv[4] = {dup2(fv.x), dup2(fv.y), dup2(fv.z), dup2(fv.w)};
#pragma unroll
        for (int s = 0; s < S; s++) {
            float4 a = *reinterpret_cast<const float4*>(&h2f[s * 32 + d0]);
            float4 b = *reinterpret_cast<const float4*>(&h2f[s * 32 + d0 + 2]);
            u64 x[4] = {pack2(a.x, a.y), pack2(a.z, a.w),
                        pack2(b.x, b.y), pack2(b.z, b.w)};
#pragma unroll
            for (int j = 0; j < 4; j++) {
                qa[s] = fma2(x[j], wq[j], qa[s]);
                ka[s] = fma2(x[j], wk[j], ka[s]);
                va[s] = fma2(x[j], wv[j], va[s]);
            }
        }
    }
    {
        u64 scl = dup2(0.35355339059327373f);
#pragma unroll
        for (int s = 0; s < S; s++) qa[s] = mul2(qa[s], scl);
    }

    // ---------------- attention: two head-pair passes, shuffle-free ---------
    const int qi = (lane >> 1) > 10 ? 10 : (lane >> 1);
    const int hl = lane & 1;
    const int hb = hl * 8;
#pragma unroll
    for (int p = 0; p < 2; p++) {
        if ((lane >> 4) == p) {
            int ld = lane & 15;
#pragma unroll
            for (int s = 0; s < S; s++) {
                stg[F2_QS + s * 16 + ld] = qa[s];
                stg[F2_KS + s * 16 + ld] = ka[s];
                stg[F2_VS + s * 16 + ld] = va[s];
            }
        }
        __syncwarp();

        u64 qr[8];
#pragma unroll
        for (int j = 0; j < 8; j += 2) {
            float4 t = *reinterpret_cast<const float4*>(&stf[F2_QS + qi * 16 + hb + j]);
            qr[j] = pack2(t.x, t.y); qr[j + 1] = pack2(t.z, t.w);
        }
        float e0[S], e1[S];
#pragma unroll
        for (int ki = 0; ki < S; ki++) {
            u64 acc = pack2(0.f, 0.f);
#pragma unroll
            for (int j = 0; j < 8; j += 2) {
                float4 kv = *reinterpret_cast<const float4*>(&stf[F2_KS + ki * 16 + hb + j]);
                acc = fma2(qr[j],     pack2(kv.x, kv.y), acc);
                acc = fma2(qr[j + 1], pack2(kv.z, kv.w), acc);
            }
            unpack2(acc, e0[ki], e1[ki]);
        }
        float m0 = e0[0], m1 = e1[0];
#pragma unroll
        for (int ki = 1; ki < S; ki++) { m0 = fmaxf(m0, e0[ki]); m1 = fmaxf(m1, e1[ki]); }
        float den0 = 0.f, den1 = 0.f;
#pragma unroll
        for (int ki = 0; ki < S; ki++) {
            e0[ki] = __expf(e0[ki] - m0); den0 += e0[ki];
            e1[ki] = __expf(e1[ki] - m1); den1 += e1[ki];
        }
        u64 cacc[8];
#pragma unroll
        for (int j = 0; j < 8; j++) cacc[j] = pack2(0.f, 0.f);
#pragma unroll
        for (int ki = 0; ki < S; ki++) {
            u64 ev = pack2(e0[ki], e1[ki]);
#pragma unroll
            for (int j = 0; j < 8; j += 2) {
                float4 vv = *reinterpret_cast<const float4*>(&stf[F2_VS + ki * 16 + hb + j]);
                cacc[j]     = fma2(ev, pack2(vv.x, vv.y), cacc[j]);
                cacc[j + 1] = fma2(ev, pack2(vv.z, vv.w), cacc[j + 1]);
            }
        }
        if (lane < 22) {
            u64 inv = pack2(1.0f / den0, 1.0f / den1);
            int cb = F2_CTX + qi * CTX_STR + (p * 2 + hl) * 8;
#pragma unroll
            for (int j = 0; j < 8; j++) stg[cb + j] = mul2(cacc[j], inv);
        }
        __syncwarp();
    }

    // ---------------- output projection + residual + LN_A (unsplit) ---------
    u64 o[S];
    {
        u64 bo = dup2(W[O_OUTB + lane]);
#pragma unroll
        for (int s = 0; s < S; s++) o[s] = bo;
    }
    for (int d0 = 0; d0 < 32; d0 += 4) {
        float4 fw = *reinterpret_cast<const float4*>(&W[O_OUTW + lane * OUTW_STR + d0]);
        u64 w0 = dup2(fw.x), w1 = dup2(fw.y), w2 = dup2(fw.z), w3 = dup2(fw.w);
#pragma unroll
        for (int s = 0; s < S; s++) {
            float4 c0 = *reinterpret_cast<const float4*>(&stf[F2_CTX + s * CTX_STR + d0]);
            float4 c1 = *reinterpret_cast<const float4*>(&stf[F2_CTX + s * CTX_STR + d0 + 2]);
            o[s] = fma2(pack2(c0.x, c0.y), w0, o[s]);
            o[s] = fma2(pack2(c0.z, c0.w), w1, o[s]);
            o[s] = fma2(pack2(c1.x, c1.y), w2, o[s]);
            o[s] = fma2(pack2(c1.z, c1.w), w3, o[s]);
        }
    }
#pragma unroll
    for (int s = 0; s < S; s++)
        o[s] = add2(o[s], h2u[s * 32 + lane]);
    __syncwarp();
    ln_apply<S>(h2u, 0, stg + F2_CTX,
                o, dup2(W[O_LNAG + lane]), dup2(W[O_LNAB + lane]), lane);

    ffn_pass<0, 6>(h2u, stg, W, lane);
    ffn_pass<6, 5>(h2u, stg, W, lane);
}

// Block 2: CLS-specialized — K/V for all tokens; V stays in registers.
// Out-proj and FFN2 split-half with scalar partials (no register pressure).
__device__ __noinline__ void block2_pair(int hoff, int soff, int lane)
{
    u64* h2u = reinterpret_cast<u64*>(&smem[hoff]);
    u64* stg = reinterpret_cast<u64*>(&smem[soff]);
    const float2* h2f = reinterpret_cast<const float2*>(h2u);
    const float2* stf = reinterpret_cast<const float2*>(stg);
    const float* W = &smem[O_BLKW];

    // ---------------- QKV: k,v all tokens; q token 0 only -------------------
    u64 ka[S], va[S];
    u64 q0 = dup2(W[O_QKVB + lane]);
    {
        u64 bk = dup2(W[O_QKVB + 32 + lane]);
        u64 bv = dup2(W[O_QKVB + 64 + lane]);
#pragma unroll
        for (int s = 0; s < S; s++) { ka[s] = bk; va[s] = bv; }
    }
    for (int d0 = 0; d0 < 32; d0 += 4) {
        float4 fq = *reinterpret_cast<const float4*>(&W[O_QKVW + lane * QKVW_STR + d0]);
        float4 fk = *reinterpret_cast<const float4*>(&W[O_QKVW + (lane + 32) * QKVW_STR + d0]);
        float4 fv = *reinterpret_cast<const float4*>(&W[O_QKVW + (lane + 64) * QKVW_STR + d0]);
        u64 wq[4] = {dup2(fq.x), dup2(fq.y), dup2(fq.z), dup2(fq.w)};
        u64 wk[4] = {dup2(fk.x), dup2(fk.y), dup2(fk.z), dup2(fk.w)};
        u64 wv[4] = {dup2(fv.x), dup2(fv.y), dup2(fv.z), dup2(fv.w)};
#pragma unroll
        for (int s = 0; s < S; s++) {
            float4 a = *reinterpret_cast<const float4*>(&h2f[s * 32 + d0]);
            float4 b = *reinterpret_cast<const float4*>(&h2f[s * 32 + d0 + 2]);
            u64 x[4] = {pack2(a.x, a.y), pack2(a.z, a.w),
                        pack2(b.x, b.y), pack2(b.z, b.w)};
#pragma unroll
            for (int j = 0; j < 4; j++) {
                ka[s] = fma2(x[j], wk[j], ka[s]);
                va[s] = fma2(x[j], wv[j], va[s]);
            }
            if (s == 0) {
#pragma unroll
                for (int j = 0; j < 4; j++) q0 = fma2(x[j], wq[j], q0);
            }
        }
    }
    q0 = mul2(q0, dup2(0.35355339059327373f));

    // stage q0 / K only (lane = dim); V stays in registers
    stg[F2_Q2 + lane] = q0;
#pragma unroll
    for (int s = 0; s < S; s++)
        stg[F2_K2 + s * 32 + lane] = ka[s];
    __syncwarp();

    // ---------------- attention row 0: lane = dim, head = lane>>3 -----------
    const int hb2 = (lane >> 3) * 8;
    u64 qr[8];
#pragma unroll
    for (int j = 0; j < 8; j += 2) {
        float4 t = *reinterpret_cast<const float4*>(&stf[F2_Q2 + hb2 + j]);
        qr[j] = pack2(t.x, t.y); qr[j + 1] = pack2(t.z, t.w);
    }
    float e0[S], e1[S];
#pragma unroll
    for (int ki = 0; ki < S; ki++) {
        u64 acc = pack2(0.f, 0.f);
#pragma unroll
        for (int j = 0; j < 8; j += 2) {
            float4 kv = *reinterpret_cast<const float4*>(&stf[F2_K2 + ki * 32 + hb2 + j]);
            acc = fma2(qr[j],     pack2(kv.x, kv.y), acc);
            acc = fma2(qr[j + 1], pack2(kv.z, kv.w), acc);
        }
        unpack2(acc, e0[ki], e1[ki]);
    }
    float m0 = e0[0], m1 = e1[0];
#pragma unroll
    for (int ki = 1; ki < S; ki++) { m0 = fmaxf(m0, e0[ki]); m1 = fmaxf(m1, e1[ki]); }
    float den0 = 0.f, den1 = 0.f;
#pragma unroll
    for (int ki = 0; ki < S; ki++) {
        e0[ki] = __expf(e0[ki] - m0); den0 += e0[ki];
        e1[ki] = __expf(e1[ki] - m1); den1 += e1[ki];
    }
    u64 c = pack2(0.f, 0.f);
#pragma unroll
    for (int ki = 0; ki < S; ki++)
        c = fma2(pack2(e0[ki], e1[ki]), va[ki], c);    // V from registers
    c = mul2(c, pack2(1.0f / den0, 1.0f / den1));
    stg[F2_C2 + lane] = c;
    __syncwarp();

    // ------------- out-proj token 0 (split-half, scalar partials) -----------
    u64 hn;
    {
        const int g  = lane >> 4;
        const int lg = lane & 15;
        u64 p0 = 0ull, p1 = 0ull;
        const float* owa = &W[O_OUTW + lg * OUTW_STR + g * 16];
        const float* owb = &W[O_OUTW + (lg + 16) * OUTW_STR + g * 16];
        for (int dd = 0; dd < 16; dd += 4) {
            float4 wa = *reinterpret_cast<const float4*>(&owa[dd]);
            float4 wb = *reinterpret_cast<const float4*>(&owb[dd]);
            float4 c0 = *reinterpret_cast<const float4*>(&stf[F2_C2 + g * 16 + dd]);
            float4 c1 = *reinterpret_cast<const float4*>(&stf[F2_C2 + g * 16 + dd + 2]);
            u64 x0 = pack2(c0.x, c0.y), x1 = pack2(c0.z, c0.w);
            u64 x2 = pack2(c1.x, c1.y), x3 = pack2(c1.z, c1.w);
            p0 = fma2(x0, dup2(wa.x), p0); p0 = fma2(x1, dup2(wa.y), p0);
            p0 = fma2(x2, dup2(wa.z), p0); p0 = fma2(x3, dup2(wa.w), p0);
            p1 = fma2(x0, dup2(wb.x), p1); p1 = fma2(x1, dup2(wb.y), p1);
            p1 = fma2(x2, dup2(wb.z), p1); p1 = fma2(x3, dup2(wb.w), p1);
        }
        u64 r0 = add2(p0, shflx2(p0, 16));
        u64 r1 = add2(p1, shflx2(p1, 16));
        u64 o = add2(add2((lane < 16) ? r0 : r1, dup2(W[O_OUTB + lane])),
                     h2u[lane]);
        hn = ln_norm(o, dup2(W[O_LNAG + lane]), dup2(W[O_LNAB + lane]));
        h2u[lane] = hn;
    }
    __syncwarp();

    // ---------------- FFN token 0 -------------------------------------------
    u64 ga[4];
#pragma unroll
    for (int j = 0; j < 4; j++) ga[j] = dup2(W[O_B1 + lane + 32 * j]);
    for (int d0 = 0; d0 < 32; d0 += 4) {
        float4 a = *reinterpret_cast<const float4*>(&h2f[d0]);
        float4 b = *reinterpret_cast<const float4*>(&h2f[d0 + 2]);
        u64 x[4] = {pack2(a.x, a.y), pack2(a.z, a.w),
                    pack2(b.x, b.y), pack2(b.z, b.w)};
#pragma unroll
        for (int j = 0; j < 4; j++) {
            float4 f = *reinterpret_cast<const float4*>(
                &W[O_W1 + (lane + 32 * j) * W1_STR + d0]);
            ga[j] = fma2(x[0], dup2(f.x), ga[j]);
            ga[j] = fma2(x[1], dup2(f.y), ga[j]);
            ga[j] = fma2(x[2], dup2(f.z), ga[j]);
            ga[j] = fma2(x[3], dup2(f.w), ga[j]);
        }
    }
#pragma unroll
    for (int j = 0; j < 4; j++) {
        float a, b; unpack2(ga[j], a, b);
        stg[F2_G2 + lane + 32 * j] = pack2(gelu1(a), gelu1(b));
    }
    __syncwarp();

    // ---- FFN2 token 0, split-half (scalar partials) ----
    {
        const int g  = lane >> 4;
        const int lg = lane & 15;
        u64 p0 = 0ull, p1 = 0ull;
        const float*  w2a = &W[O_W2 + lg * W2_STR + g * 64];
        const float*  w2b = &W[O_W2 + (lg + 16) * W2_STR + g * 64];
        const float2* gh  = &stf[F2_G2 + g * 64];
        for (int fo = 0; fo < 64; fo += 4) {
            float4 wa = *reinterpret_cast<const float4*>(&w2a[fo]);
            float4 wb = *reinterpret_cast<const float4*>(&w2b[fo]);
            float4 a = *reinterpret_cast<const float4*>(&gh[fo]);
            float4 b = *reinterpret_cast<const float4*>(&gh[fo + 2]);
            u64 x0 = pack2(a.x, a.y), x1 = pack2(a.z, a.w);
            u64 x2 = pack2(b.x, b.y), x3 = pack2(b.z, b.w);
            p0 = fma2(x0, dup2(wa.x), p0); p0 = fma2(x1, dup2(wa.y), p0);
            p0 = fma2(x2, dup2(wa.z), p0); p0 = fma2(x3, dup2(wa.w), p0);
            p1 = fma2(x0, dup2(wb.x), p1); p1 = fma2(x1, dup2(wb.y), p1);
            p1 = fma2(x2, dup2(wb.z), p1); p1 = fma2(x3, dup2(wb.w), p1);
        }
        u64 r0 = add2(p0, shflx2(p0, 16));
        u64 r1 = add2(p1, shflx2(p1, 16));
        u64 o2 = add2(add2((lane < 16) ? r0 : r1, dup2(W[O_B2 + lane])), hn);
        h2u[lane] = ln_norm(o2, dup2(W[O_LNBG + lane]), dup2(W[O_LNBB + lane]));
    }
    __syncwarp();
}

__global__ void __launch_bounds__(THREADS)
tab_transformer_kernel(KParams p)
{
    const int tid = threadIdx.x;

    for (int i = tid; i < 320; i += THREADS) smem[O_WFEAT + i] = p.in[1][i];
    for (int i = tid; i < 320; i += THREADS) smem[O_BFEAT + i] = p.in[2][i];
    if (tid < 32) {
        smem[O_CLS  + tid] = p.in[3][tid];
        smem[O_CLFW + tid] = p.in[28][tid];
    }
    if (tid == 0) smem[O_CLFB] = p.in[29][0];
    stage_block(&smem[O_BLKW], &p.in[4], tid);
    __syncthreads();

    const int warp = tid >> 5, lane = tid & 31;
    int pr = blockIdx.x * NW + warp;
    const bool valid = (pr < NPAIR);
    if (!valid) pr = NPAIR - 1;
    const int b0 = pr * 2;

    const int hoff = O_ACT + warp * ACT_F;
    const int soff = hoff + H2_F;
    u64* h2u = reinterpret_cast<u64*>(&smem[hoff]);

    float xv0 = (lane < 10) ? p.in[0][(size_t)b0 * 10 + lane] : 0.f;
    float xv1 = (lane < 10) ? p.in[0][(size_t)(b0 + 1) * 10 + lane] : 0.f;
    h2u[lane] = dup2(smem[O_CLS + lane]);
#pragma unroll
    for (int i = 0; i < 10; i++) {
        float a = __shfl_sync(0xffffffffu, xv0, i);
        float b = __shfl_sync(0xffffffffu, xv1, i);
        u64 w  = dup2(smem[O_WFEAT + i * 32 + lane]);
        u64 bb = dup2(smem[O_BFEAT + i * 32 + lane]);
        h2u[(i + 1) * 32 + lane] = fma2(pack2(a, b), w, bb);
    }
    __syncwarp();

    block_pair(hoff, soff, lane);

    __syncthreads();
    stage_block(&smem[O_BLKW], &p.in[16], tid);
    __syncthreads();

    block2_pair(hoff, soff, lane);

    u64 v = mul2(h2u[lane], dup2(smem[O_CLFW + lane]));
#pragma unroll
    for (int mk = 16; mk; mk >>= 1) v = add2(v, shflx2(v, mk));
    if (valid && lane == 0) {
        float r0, r1; unpack2(v, r0, r1);
        float cb = smem[O_CLFB];
        *reinterpret_cast<float2*>(&p.out[b0]) = make_float2(r0 + cb, r1 + cb);
    }
}

extern "C" void kernel_launch(void* const* d_in, const int* in_sizes, int n_in,
                              void* d_out, int out_size)
{
    (void)in_sizes; (void)n_in; (void)out_size;
    KParams p;
    for (int i = 0; i < 30; i++) p.in[i] = (const float*)d_in[i];
    p.out = (float*)d_out;

    cudaFuncSetAttribute(tab_transformer_kernel,
                         cudaFuncAttributeMaxDynamicSharedMemorySize, SMEM_BYTES);

    const int grid = (NPAIR + NW - 1) / NW;   // 4096
    tab_transformer_kernel<<<grid, THREADS, SMEM_BYTES>>>(p);
}

// round 14
// speedup vs baseline: 1.6033x; 1.0031x over previous
#include <cuda_runtime.h>

// Fused 2-block tiny-transformer, 131072 sequences. One warp = TWO batches
// packed as f32x2. Block 1: full 11-token block; FFN2 split-half (SN<=6
// partial arrays — fits registers); out-proj UNSPLIT (S=11 partials spill).
// Block 2: CLS-specialized; V in registers; out-proj + FFN2 split-half with
// scalar partials.

namespace {
constexpr int S  = 11;
constexpr int NW = 16;
constexpr int THREADS = NW * 32;                  // 512
constexpr int BTOT = 131072;
constexpr int NPAIR = BTOT / 2;                   // 65536

// --- per-block weight layout (floats), output-major rows, stride%32==4 ------
constexpr int QKVW_STR = 36;
constexpr int OUTW_STR = 36;
constexpr int W1_STR   = 36;
constexpr int W2_STR   = 132;

constexpr int O_QKVW = 0;
constexpr int O_QKVB = O_QKVW + 96 * QKVW_STR;    // 3456
constexpr int O_OUTW = O_QKVB + 96;               // 3552
constexpr int O_OUTB = O_OUTW + 32 * OUTW_STR;    // 4704
constexpr int O_LNAG = O_OUTB + 32;
constexpr int O_LNAB = O_LNAG + 32;
constexpr int O_W1   = O_LNAB + 32;               // 4800
constexpr int O_B1   = O_W1 + 128 * W1_STR;       // 9408
constexpr int O_W2   = O_B1 + 128;                // 9536
constexpr int O_B2   = O_W2 + 32 * W2_STR;        // 13760
constexpr int O_LNBG = O_B2 + 32;
constexpr int O_LNBB = O_LNBG + 32;
constexpr int BLK_SZ = O_LNBB + 32;               // 13856

// --- global smem layout (floats) ---
constexpr int O_WFEAT = 0;
constexpr int O_BFEAT = O_WFEAT + 320;
constexpr int O_CLS   = O_BFEAT + 320;
constexpr int O_CLFW  = O_CLS + 32;
constexpr int O_CLFB  = O_CLFW + 32;
constexpr int O_BLKW  = 720;
constexpr int O_ACT   = O_BLKW + BLK_SZ;          // 14576

// per-warp activation region (floats)
constexpr int H2_F   = 12 * 32 * 2;               // h2 [12][32] float2 = 768
// block1 staging (float2 units): q[11][16], k[11][16], v[11][16], ctx[11][34]
constexpr int F2_QS  = 0;
constexpr int F2_KS  = 176;
constexpr int F2_VS  = 352;
constexpr int F2_CTX = 528;
constexpr int CTX_STR = 34;
constexpr int LN_MU  = 374;                       // mu/sig offset in LN buf
// block2 staging (float2 units): q0[32], k[11][32], ctx[32]
constexpr int F2_Q2  = 0;
constexpr int F2_K2  = 32;
constexpr int F2_C2  = 736;
constexpr int F2_G2  = 0;                         // ffn g buffer (reuse)
constexpr int STG_F2 = 928;
constexpr int ACT_F  = H2_F + STG_F2 * 2;         // 2624 floats / warp
constexpr int SMEM_FLOATS = O_ACT + NW * ACT_F;   // 56560
constexpr int SMEM_BYTES  = SMEM_FLOATS * 4;      // 226240
}

extern __shared__ float smem[];

using u64 = unsigned long long;

static __device__ __forceinline__ u64 pack2(float x, float y) {
    u64 r; asm("mov.b64 %0,{%1,%2};" : "=l"(r) : "f"(x), "f"(y)); return r;
}
static __device__ __forceinline__ void unpack2(u64 v, float& x, float& y) {
    asm("mov.b64 {%0,%1},%2;" : "=f"(x), "=f"(y) : "l"(v));
}
static __device__ __forceinline__ u64 dup2(float x) { return pack2(x, x); }
static __device__ __forceinline__ u64 fma2(u64 a, u64 b, u64 c) {
    u64 d; asm("fma.rn.f32x2 %0,%1,%2,%3;" : "=l"(d) : "l"(a), "l"(b), "l"(c)); return d;
}
static __device__ __forceinline__ u64 add2(u64 a, u64 b) {
    u64 d; asm("add.rn.f32x2 %0,%1,%2;" : "=l"(d) : "l"(a), "l"(b)); return d;
}
static __device__ __forceinline__ u64 mul2(u64 a, u64 b) {
    u64 d; asm("mul.rn.f32x2 %0,%1,%2;" : "=l"(d) : "l"(a), "l"(b)); return d;
}
static __device__ __forceinline__ u64 neg2(u64 x) {
    return x ^ 0x8000000080000000ULL;
}
static __device__ __forceinline__ u64 shflx2(u64 v, int m) {
    float x, y; unpack2(v, x, y);
    x = __shfl_xor_sync(0xffffffffu, x, m);
    y = __shfl_xor_sync(0xffffffffu, y, m);
    return pack2(x, y);
}
static __device__ __forceinline__ float gelu1(float x) {
    return 0.5f * x * (1.0f + erff(x * 0.7071067811865475f));
}
// single-token LN via butterfly (block 2)
static __device__ __forceinline__ u64 ln_norm(u64 v, u64 lg, u64 lb) {
    u64 sum = v, sq = mul2(v, v);
#pragma unroll
    for (int mk = 16; mk; mk >>= 1) {
        sum = add2(sum, shflx2(sum, mk));
        sq  = add2(sq,  shflx2(sq,  mk));
    }
    float s0, s1, q0, q1, v0, v1;
    unpack2(sum, s0, s1); unpack2(sq, q0, q1); unpack2(v, v0, v1);
    float mu0 = s0 * 0.03125f, mu1 = s1 * 0.03125f;
    float r0 = rsqrtf(fmaf(-mu0, mu0, q0 * 0.03125f) + 1e-5f);
    float r1 = rsqrtf(fmaf(-mu1, mu1, q1 * 0.03125f) + 1e-5f);
    return fma2(pack2((v0 - mu0) * r0, (v1 - mu1) * r1), lg, lb);
}

struct KParams {
    const float* in[30];
    float* out;
};

// Staged LayerNorm over SN tokens (block 1): stats by lane t, applied by all.
template <int SN>
static __device__ __forceinline__ void ln_apply(u64* h2u, int hbase, u64* buf,
                                                const u64* v, u64 lg, u64 lb,
                                                int lane)
{
#pragma unroll
    for (int t = 0; t < SN; t++) buf[t * 34 + lane] = v[t];
    __syncwarp();
    if (lane < SN) {
        const float2* row = reinterpret_cast<const float2*>(&buf[lane * 34]);
        u64 s = pack2(0.f, 0.f), q = pack2(0.f, 0.f);
#pragma unroll
        for (int i = 0; i < 16; i++) {
            float4 c = *reinterpret_cast<const float4*>(&row[i * 2]);
            u64 a = pack2(c.x, c.y), b = pack2(c.z, c.w);
            s = add2(s, add2(a, b));
            q = fma2(a, a, q); q = fma2(b, b, q);
        }
        float s0, s1, q0, q1;
        unpack2(s, s0, s1); unpack2(q, q0, q1);
        float mu0 = s0 * 0.03125f, mu1 = s1 * 0.03125f;
        float r0 = rsqrtf(fmaf(-mu0, mu0, q0 * 0.03125f) + 1e-5f);
        float r1 = rsqrtf(fmaf(-mu1, mu1, q1 * 0.03125f) + 1e-5f);
        *reinterpret_cast<float4*>(&buf[LN_MU + 2 * lane]) =
            make_float4(mu0, mu1, r0, r1);
    }
    __syncwarp();
#pragma unroll
    for (int t = 0; t < SN; t++) {
        float4 ms = *reinterpret_cast<const float4*>(&buf[LN_MU + 2 * t]);
        u64 mu = pack2(ms.x, ms.y), rs = pack2(ms.z, ms.w);
        u64 t1 = mul2(rs, lg);
        h2u[hbase + t * 32 + lane] = fma2(v[t], t1, add2(lb, neg2(mul2(mu, t1))));
    }
    __syncwarp();
}

// Stage one block's weights: straight strided float4 copies (output-major).
static __device__ __forceinline__ void stage_block(float* W, const float* const* q,
                                                   int tid)
{
    for (int i4 = tid; i4 < 768; i4 += THREADS) {         // qkv [96][32]
        float4 v = reinterpret_cast<const float4*>(q[0])[i4];
        int e = i4 >> 3, c = (i4 & 7) * 4;
        *reinterpret_cast<float4*>(&W[O_QKVW + e * QKVW_STR + c]) = v;
    }
    for (int i = tid; i < 96; i += THREADS) W[O_QKVB + i] = q[1][i];
    for (int i4 = tid; i4 < 256; i4 += THREADS) {         // out_w [32][32]
        float4 v = reinterpret_cast<const float4*>(q[2])[i4];
        int e = i4 >> 3, c = (i4 & 7) * 4;
        *reinterpret_cast<float4*>(&W[O_OUTW + e * OUTW_STR + c]) = v;
    }
    if (tid < 32) {
        W[O_OUTB + tid] = q[3][tid];
        W[O_LNAG + tid] = q[4][tid];
        W[O_LNAB + tid] = q[5][tid];
    }
    for (int i4 = tid; i4 < 1024; i4 += THREADS) {        // w1 [128][32]
        float4 v = reinterpret_cast<const float4*>(q[6])[i4];
        int f = i4 >> 3, c = (i4 & 7) * 4;
        *reinterpret_cast<float4*>(&W[O_W1 + f * W1_STR + c]) = v;
    }
    for (int i = tid; i < 128; i += THREADS) W[O_B1 + i] = q[7][i];
    for (int i4 = tid; i4 < 1024; i4 += THREADS) {        // w2 [32][128]
        float4 v = reinterpret_cast<const float4*>(q[8])[i4];
        int d = i4 >> 5, c = (i4 & 31) * 4;
        *reinterpret_cast<float4*>(&W[O_W2 + d * W2_STR + c]) = v;
    }
    if (tid < 32) {
        W[O_B2   + tid] = q[9][tid];
        W[O_LNBG + tid] = q[10][tid];
        W[O_LNBB + tid] = q[11][tid];
    }
}

// FFN over tokens [SB, SB+SN) (block 1): FFN1 -> GELU -> FFN2 split-half
// -> +res -> LN_B.
template <int SB, int SN>
static __device__ __forceinline__ void ffn_pass(u64* h2u, u64* g2u,
                                                const float* W, int lane)
{
    const float2* g2f = reinterpret_cast<const float2*>(g2u);
    const float2* h2f = reinterpret_cast<const float2*>(h2u);

    // ---- FFN1: 32 -> 128 ----
    u64 ga[4][SN];
#pragma unroll
    for (int j = 0; j < 4; j++) {
        u64 b = dup2(W[O_B1 + lane + 32 * j]);
#pragma unroll
        for (int t = 0; t < SN; t++) ga[j][t] = b;
    }
    for (int d0 = 0; d0 < 32; d0 += 4) {
        u64 w[4][4];
#pragma unroll
        for (int j = 0; j < 4; j++) {
            float4 f = *reinterpret_cast<const float4*>(
                &W[O_W1 + (lane + 32 * j) * W1_STR + d0]);
            w[j][0] = dup2(f.x); w[j][1] = dup2(f.y);
            w[j][2] = dup2(f.z); w[j][3] = dup2(f.w);
        }
#pragma unroll
        for (int t = 0; t < SN; t++) {
            float4 a = *reinterpret_cast<const float4*>(&h2f[(SB + t) * 32 + d0]);
            float4 b = *reinterpret_cast<const float4*>(&h2f[(SB + t) * 32 + d0 + 2]);
            u64 x[4] = {pack2(a.x, a.y), pack2(a.z, a.w),
                        pack2(b.x, b.y), pack2(b.z, b.w)};
#pragma unroll
            for (int j = 0; j < 4; j++)
#pragma unroll
                for (int m = 0; m < 4; m++)
                    ga[j][t] = fma2(x[m], w[j][m], ga[j][t]);
        }
    }
#pragma unroll
    for (int j = 0; j < 4; j++)
#pragma unroll
        for (int t = 0; t < SN; t++) {
            float a, b; unpack2(ga[j][t], a, b);
            g2u[t * 128 + lane + 32 * j] = pack2(gelu1(a), gelu1(b));
        }
    __syncwarp();

    // ---- FFN2: 128 -> 32, split-half across lane groups ----
    const int g  = lane >> 4;
    const int lg = lane & 15;
    u64 p0[SN], p1[SN];
#pragma unroll
    for (int t = 0; t < SN; t++) { p0[t] = 0ull; p1[t] = 0ull; }
    const float*  w2a = &W[O_W2 + lg * W2_STR + g * 64];
    const float*  w2b = &W[O_W2 + (lg + 16) * W2_STR + g * 64];
    const float2* gh  = &g2f[g * 64];            // f2 offset of this f-half
    for (int fo = 0; fo < 64; fo += 4) {
        float4 wa = *reinterpret_cast<const float4*>(&w2a[fo]);
        float4 wb = *reinterpret_cast<const float4*>(&w2b[fo]);
        u64 wa0 = dup2(wa.x), wa1 = dup2(wa.y), wa2 = dup2(wa.z), wa3 = dup2(wa.w);
        u64 wb0 = dup2(wb.x), wb1 = dup2(wb.y), wb2 = dup2(wb.z), wb3 = dup2(wb.w);
#pragma unroll
        for (int t = 0; t < SN; t++) {
            float4 a = *reinterpret_cast<const float4*>(&gh[t * 128 + fo]);
            float4 b = *reinterpret_cast<const float4*>(&gh[t * 128 + fo + 2]);
            u64 x0 = pack2(a.x, a.y), x1 = pack2(a.z, a.w);
            u64 x2 = pack2(b.x, b.y), x3 = pack2(b.z, b.w);
            p0[t] = fma2(x0, wa0, p0[t]); p0[t] = fma2(x1, wa1, p0[t]);
            p0[t] = fma2(x2, wa2, p0[t]); p0[t] = fma2(x3, wa3, p0[t]);
            p1[t] = fma2(x0, wb0, p1[t]); p1[t] = fma2(x1, wb1, p1[t]);
            p1[t] = fma2(x2, wb2, p1[t]); p1[t] = fma2(x3, wb3, p1[t]);
        }
    }
    u64 o2[SN];
    {
        u64 bias = dup2(W[O_B2 + lane]);
#pragma unroll
        for (int t = 0; t < SN; t++) {
            u64 r0 = add2(p0[t], shflx2(p0[t], 16));
            u64 r1 = add2(p1[t], shflx2(p1[t], 16));
            o2[t] = add2(add2((lane < 16) ? r0 : r1, bias),
                         h2u[(SB + t) * 32 + lane]);
        }
    }
    __syncwarp();
    ln_apply<SN>(h2u, SB * 32, g2u,
                 o2, dup2(W[O_LNBG + lane]), dup2(W[O_LNBB + lane]), lane);
}

// Block 1: full transformer block for a packed batch-pair.
__device__ __noinline__ void block_pair(int hoff, int soff, int lane)
{
    u64* h2u = reinterpret_cast<u64*>(&smem[hoff]);
    u64* stg = reinterpret_cast<u64*>(&smem[soff]);
    const float2* h2f = reinterpret_cast<const float2*>(h2u);
    const float2* stf = reinterpret_cast<const float2*>(stg);
    const float* W = &smem[O_BLKW];

    // ---------------- QKV projection (lane = output dim) ----------------
    u64 qa[S], ka[S], va[S];
    {
        u64 bq = dup2(W[O_QKVB + lane]);
        u64 bk = dup2(W[O_QKVB + 32 + lane]);
        u64 bv = dup2(W[O_QKVB + 64 + lane]);
#pragma unroll
        for (int s = 0; s < S; s++) { qa[s] = bq; ka[s] = bk; va[s] = bv; }
    }
    for (int d0 = 0; d0 < 32; d0 += 4) {
        float4 fq = *reinterpret_cast<const float4*>(&W[O_QKVW + lane * QKVW_STR + d0]);
        float4 fk = *reinterpret_cast<const float4*>(&W[O_QKVW + (lane + 32) * QKVW_STR + d0]);
        float4 fv = *reinterpret_cast<const float4*>(&W[O_QKVW + (lane + 64) * QKVW_STR + d0]);
        u64 wq[4] = {dup2(fq.x), dup2(fq.y), dup2(fq.z), dup2(fq.w)};
        u64 wk[4] = {dup2(fk.x), dup2(fk.y), dup2(fk.z), dup2(fk.w)};
        u64 wv[4] = {dup2(fv.x), dup2(fv.y), dup2(fv.z), dup2(fv.w)};
#pragma unroll
        for (int s = 0; s < S; s++) {
            float4 a = *reinterpret_cast<const float4*>(&h2f[s * 32 + d0]);
            float4 b = *reinterpret_cast<const float4*>(&h2f[s * 32 + d0 + 2]);
            u64 x[4] = {pack2(a.x, a.y), pack2(a.z, a.w),
                        pack2(b.x, b.y), pack2(b.z, b.w)};
#pragma unroll
            for (int j = 0; j < 4; j++) {
                qa[s] = fma2(x[j], wq[j], qa[s]);
                ka[s] = fma2(x[j], wk[j], ka[s]);
                va[s] = fma2(x[j], wv[j], va[s]);
            }
        }
    }
    {
        u64 scl = dup2(0.35355339059327373f);
#pragma unroll
        for (int s = 0; s < S; s++) qa[s] = mul2(qa[s], scl);
    }

    // ---------------- attention: two head-pair passes, shuffle-free ---------
    const int qi = (lane >> 1) > 10 ? 10 : (lane >> 1);
    const int hl = lane & 1;
    const int hb = hl * 8;
#pragma unroll
    for (int p = 0; p < 2; p++) {
        if ((lane >> 4) == p) {
            int ld = lane & 15;
#pragma unroll
            for (int s = 0; s < S; s++) {
                stg[F2_QS + s * 16 + ld] = qa[s];
                stg[F2_KS + s * 16 + ld] = ka[s];
                stg[F2_VS + s * 16 + ld] = va[s];
            }
        }
        __syncwarp();

        u64 qr[8];
#pragma unroll
        for (int j = 0; j < 8; j += 2) {
            float4 t = *reinterpret_cast<const float4*>(&stf[F2_QS + qi * 16 + hb + j]);
            qr[j] = pack2(t.x, t.y); qr[j + 1] = pack2(t.z, t.w);
        }
        float e0[S], e1[S];
#pragma unroll
        for (int ki = 0; ki < S; ki++) {
            u64 acc = pack2(0.f, 0.f);
#pragma unroll
            for (int j = 0; j < 8; j += 2) {
                float4 kv = *reinterpret_cast<const float4*>(&stf[F2_KS + ki * 16 + hb + j]);
                acc = fma2(qr[j],     pack2(kv.x, kv.y), acc);
                acc = fma2(qr[j + 1], pack2(kv.z, kv.w), acc);
            }
            unpack2(acc, e0[ki], e1[ki]);
        }
        float m0 = e0[0], m1 = e1[0];
#pragma unroll
        for (int ki = 1; ki < S; ki++) { m0 = fmaxf(m0, e0[ki]); m1 = fmaxf(m1, e1[ki]); }
        float den0 = 0.f, den1 = 0.f;
#pragma unroll
        for (int ki = 0; ki < S; ki++) {
            e0[ki] = __expf(e0[ki] - m0); den0 += e0[ki];
            e1[ki] = __expf(e1[ki] - m1); den1 += e1[ki];
        }
        u64 cacc[8];
#pragma unroll
        for (int j = 0; j < 8; j++) cacc[j] = pack2(0.f, 0.f);
#pragma unroll
        for (int ki = 0; ki < S; ki++) {
            u64 ev = pack2(e0[ki], e1[ki]);
#pragma unroll
            for (int j = 0; j < 8; j += 2) {
                float4 vv = *reinterpret_cast<const float4*>(&stf[F2_VS + ki * 16 + hb + j]);
                cacc[j]     = fma2(ev, pack2(vv.x, vv.y), cacc[j]);
                cacc[j + 1] = fma2(ev, pack2(vv.z, vv.w), cacc[j + 1]);
            }
        }
        if (lane < 22) {
            u64 inv = pack2(1.0f / den0, 1.0f / den1);
            int cb = F2_CTX + qi * CTX_STR + (p * 2 + hl) * 8;
#pragma unroll
            for (int j = 0; j < 8; j++) stg[cb + j] = mul2(cacc[j], inv);
        }
        __syncwarp();
    }

    // ---------------- output projection + residual + LN_A (unsplit) ---------
    u64 o[S];
    {
        u64 bo = dup2(W[O_OUTB + lane]);
#pragma unroll
        for (int s = 0; s < S; s++) o[s] = bo;
    }
    for (int d0 = 0; d0 < 32; d0 += 4) {
        float4 fw = *reinterpret_cast<const float4*>(&W[O_OUTW + lane * OUTW_STR + d0]);
        u64 w0 = dup2(fw.x), w1 = dup2(fw.y), w2 = dup2(fw.z), w3 = dup2(fw.w);
#pragma unroll
        for (int s = 0; s < S; s++) {
            float4 c0 = *reinterpret_cast<const float4*>(&stf[F2_CTX + s * CTX_STR + d0]);
            float4 c1 = *reinterpret_cast<const float4*>(&stf[F2_CTX + s * CTX_STR + d0 + 2]);
            o[s] = fma2(pack2(c0.x, c0.y), w0, o[s]);
            o[s] = fma2(pack2(c0.z, c0.w), w1, o[s]);
            o[s] = fma2(pack2(c1.x, c1.y), w2, o[s]);
            o[s] = fma2(pack2(c1.z, c1.w), w3, o[s]);
        }
    }
#pragma unroll
    for (int s = 0; s < S; s++)
        o[s] = add2(o[s], h2u[s * 32 + lane]);
    __syncwarp();
    ln_apply<S>(h2u, 0, stg + F2_CTX,
                o, dup2(W[O_LNAG + lane]), dup2(W[O_LNAB + lane]), lane);

    ffn_pass<0, 6>(h2u, stg, W, lane);
    ffn_pass<6, 5>(h2u, stg, W, lane);
}

// Block 2: CLS-specialized — K/V for all tokens; V stays in registers.
// Out-proj and FFN2 split-half with scalar partials (no register pressure).
__device__ __noinline__ void block2_pair(int hoff, int soff, int lane)
{
    u64* h2u = reinterpret_cast<u64*>(&smem[hoff]);
    u64* stg = reinterpret_cast<u64*>(&smem[soff]);
    const float2* h2f = reinterpret_cast<const float2*>(h2u);
    const float2* stf = reinterpret_cast<const float2*>(stg);
    const float* W = &smem[O_BLKW];

    // ---------------- QKV: k,v all tokens; q token 0 only -------------------
    u64 ka[S], va[S];
    u64 q0 = dup2(W[O_QKVB + lane]);
    {
        u64 bk = dup2(W[O_QKVB + 32 + lane]);
        u64 bv = dup2(W[O_QKVB + 64 + lane]);
#pragma unroll
        for (int s = 0; s < S; s++) { ka[s] = bk; va[s] = bv; }
    }
    for (int d0 = 0; d0 < 32; d0 += 4) {
        float4 fq = *reinterpret_cast<const float4*>(&W[O_QKVW + lane * QKVW_STR + d0]);
        float4 fk = *reinterpret_cast<const float4*>(&W[O_QKVW + (lane + 32) * QKVW_STR + d0]);
        float4 fv = *reinterpret_cast<const float4*>(&W[O_QKVW + (lane + 64) * QKVW_STR + d0]);
        u64 wq[4] = {dup2(fq.x), dup2(fq.y), dup2(fq.z), dup2(fq.w)};
        u64 wk[4] = {dup2(fk.x), dup2(fk.y), dup2(fk.z), dup2(fk.w)};
        u64 wv[4] = {dup2(fv.x), dup2(fv.y), dup2(fv.z), dup2(fv.w)};
#pragma unroll
        for (int s = 0; s < S; s++) {
            float4 a = *reinterpret_cast<const float4*>(&h2f[s * 32 + d0]);
            float4 b = *reinterpret_cast<const float4*>(&h2f[s * 32 + d0 + 2]);
            u64 x[4] = {pack2(a.x, a.y), pack2(a.z, a.w),
                        pack2(b.x, b.y), pack2(b.z, b.w)};
#pragma unroll
            for (int j = 0; j < 4; j++) {
                ka[s] = fma2(x[j], wk[j], ka[s]);
                va[s] = fma2(x[j], wv[j], va[s]);
            }
            if (s == 0) {
#pragma unroll
                for (int j = 0; j < 4; j++) q0 = fma2(x[j], wq[j], q0);
            }
        }
    }
    q0 = mul2(q0, dup2(0.35355339059327373f));

    // stage q0 / K only (lane = dim); V stays in registers
    stg[F2_Q2 + lane] = q0;
#pragma unroll
    for (int s = 0; s < S; s++)
        stg[F2_K2 + s * 32 + lane] = ka[s];
    __syncwarp();

    // ---------------- attention row 0: lane = dim, head = lane>>3 -----------
    const int hb2 = (lane >> 3) * 8;
    u64 qr[8];
#pragma unroll
    for (int j = 0; j < 8; j += 2) {
        float4 t = *reinterpret_cast<const float4*>(&stf[F2_Q2 + hb2 + j]);
        qr[j] = pack2(t.x, t.y); qr[j + 1] = pack2(t.z, t.w);
    }
    float e0[S], e1[S];
#pragma unroll
    for (int ki = 0; ki < S; ki++) {
        u64 acc = pack2(0.f, 0.f);
#pragma unroll
        for (int j = 0; j < 8; j += 2) {
            float4 kv = *reinterpret_cast<const float4*>(&stf[F2_K2 + ki * 32 + hb2 + j]);
            acc = fma2(qr[j],     pack2(kv.x, kv.y), acc);
            acc = fma2(qr[j + 1], pack2(kv.z, kv.w), acc);
        }
        unpack2(acc, e0[ki], e1[ki]);
    }
    float m0 = e0[0], m1 = e1[0];
#pragma unroll
    for (int ki = 1; ki < S; ki++) { m0 = fmaxf(m0, e0[ki]); m1 = fmaxf(m1, e1[ki]); }
    float den0 = 0.f, den1 = 0.f;
#pragma unroll
    for (int ki = 0; ki < S; ki++) {
        e0[ki] = __expf(e0[ki] - m0); den0 += e0[ki];
        e1[ki] = __expf(e1[ki] - m1); den1 += e1[ki];
    }
    u64 c = pack2(0.f, 0.f);
#pragma unroll
    for (int ki = 0; ki < S; ki++)
        c = fma2(pack2(e0[ki], e1[ki]), va[ki], c);    // V from registers
    c = mul2(c, pack2(1.0f / den0, 1.0f / den1));
    stg[F2_C2 + lane] = c;
    __syncwarp();

    // ------------- out-proj token 0 (split-half, scalar partials) -----------
    u64 hn;
    {
        const int g  = lane >> 4;
        const int lg = lane & 15;
        u64 p0 = 0ull, p1 = 0ull;
        const float* owa = &W[O_OUTW + lg * OUTW_STR + g * 16];
        const float* owb = &W[O_OUTW + (lg + 16) * OUTW_STR + g * 16];
        for (int dd = 0; dd < 16; dd += 4) {
            float4 wa = *reinterpret_cast<const float4*>(&owa[dd]);
            float4 wb = *reinterpret_cast<const float4*>(&owb[dd]);
            float4 c0 = *reinterpret_cast<const float4*>(&stf[F2_C2 + g * 16 + dd]);
            float4 c1 = *reinterpret_cast<const float4*>(&stf[F2_C2 + g * 16 + dd + 2]);
            u64 x0 = pack2(c0.x, c0.y), x1 = pack2(c0.z, c0.w);
            u64 x2 = pack2(c1.x, c1.y), x3 = pack2(c1.z, c1.w);
            p0 = fma2(x0, dup2(wa.x), p0); p0 = fma2(x1, dup2(wa.y), p0);
            p0 = fma2(x2, dup2(wa.z), p0); p0 = fma2(x3, dup2(wa.w), p0);
            p1 = fma2(x0, dup2(wb.x), p1); p1 = fma2(x1, dup2(wb.y), p1);
            p1 = fma2(x2, dup2(wb.z), p1); p1 = fma2(x3, dup2(wb.w), p1);
        }
        u64 r0 = add2(p0, shflx2(p0, 16));
        u64 r1 = add2(p1, shflx2(p1, 16));
        u64 o = add2(add2((lane < 16) ? r0 : r1, dup2(W[O_OUTB + lane])),
                     h2u[lane]);
        hn = ln_norm(o, dup2(W[O_LNAG + lane]), dup2(W[O_LNAB + lane]));
        h2u[lane] = hn;
    }
    __syncwarp();

    // ---------------- FFN token 0 -------------------------------------------
    u64 ga[4];
#pragma unroll
    for (int j = 0; j < 4; j++) ga[j] = dup2(W[O_B1 + lane + 32 * j]);
    for (int d0 = 0; d0 < 32; d0 += 4) {
        float4 a = *reinterpret_cast<const float4*>(&h2f[d0]);
        float4 b = *reinterpret_cast<const float4*>(&h2f[d0 + 2]);
        u64 x[4] = {pack2(a.x, a.y), pack2(a.z, a.w),
                    pack2(b.x, b.y), pack2(b.z, b.w)};
#pragma unroll
        for (int j = 0; j < 4; j++) {
            float4 f = *reinterpret_cast<const float4*>(
                &W[O_W1 + (lane + 32 * j) * W1_STR + d0]);
            ga[j] = fma2(x[0], dup2(f.x), ga[j]);
            ga[j] = fma2(x[1], dup2(f.y), ga[j]);
            ga[j] = fma2(x[2], dup2(f.z), ga[j]);
            ga[j] = fma2(x[3], dup2(f.w), ga[j]);
        }
    }
#pragma unroll
    for (int j = 0; j < 4; j++) {
        float a, b; unpack2(ga[j], a, b);
        stg[F2_G2 + lane + 32 * j] = pack2(gelu1(a), gelu1(b));
    }
    __syncwarp();

    // ---- FFN2 token 0, split-half (scalar partials) ----
    {
        const int g  = lane >> 4;
        const int lg = lane & 15;
        u64 p0 = 0ull, p1 = 0ull;
        const float*  w2a = &W[O_W2 + lg * W2_STR + g * 64];
        const float*  w2b = &W[O_W2 + (lg + 16) * W2_STR + g * 64];
        const float2* gh  = &stf[F2_G2 + g * 64];
        for (int fo = 0; fo < 64; fo += 4) {
            float4 wa = *reinterpret_cast<const float4*>(&w2a[fo]);
            float4 wb = *reinterpret_cast<const float4*>(&w2b[fo]);
            float4 a = *reinterpret_cast<const float4*>(&gh[fo]);
            float4 b = *reinterpret_cast<const float4*>(&gh[fo + 2]);
            u64 x0 = pack2(a.x, a.y), x1 = pack2(a.z, a.w);
            u64 x2 = pack2(b.x, b.y), x3 = pack2(b.z, b.w);
            p0 = fma2(x0, dup2(wa.x), p0); p0 = fma2(x1, dup2(wa.y), p0);
            p0 = fma2(x2, dup2(wa.z), p0); p0 = fma2(x3, dup2(wa.w), p0);
            p1 = fma2(x0, dup2(wb.x), p1); p1 = fma2(x1, dup2(wb.y), p1);
            p1 = fma2(x2, dup2(wb.z), p1); p1 = fma2(x3, dup2(wb.w), p1);
        }
        u64 r0 = add2(p0, shflx2(p0, 16));
        u64 r1 = add2(p1, shflx2(p1, 16));
        u64 o2 = add2(add2((lane < 16) ? r0 : r1, dup2(W[O_B2 + lane])), hn);
        h2u[lane] = ln_norm(o2, dup2(W[O_LNBG + lane]), dup2(W[O_LNBB + lane]));
    }
    __syncwarp();
}

__global__ void __launch_bounds__(THREADS)
tab_transformer_kernel(KParams p)
{
    const int tid = threadIdx.x;

    for (int i = tid; i < 320; i += THREADS) smem[O_WFEAT + i] = p.in[1][i];
    for (int i = tid; i < 320; i += THREADS) smem[O_BFEAT + i] = p.in[2][i];
    if (tid < 32) {
        smem[O_CLS  + tid] = p.in[3][tid];
        smem[O_CLFW + tid] = p.in[28][tid];
    }
    if (tid == 0) smem[O_CLFB] = p.in[29][0];
    stage_block(&smem[O_BLKW], &p.in[4], tid);
    __syncthreads();

    const int warp = tid >> 5, lane = tid & 31;
    int pr = blockIdx.x * NW + warp;
    const bool valid = (pr < NPAIR);
    if (!valid) pr = NPAIR - 1;
    const int b0 = pr * 2;

    const int hoff = O_ACT + warp * ACT_F;
    const int soff = hoff + H2_F;
    u64* h2u = reinterpret_cast<u64*>(&smem[hoff]);

    float xv0 = (lane < 10) ? p.in[0][(size_t)b0 * 10 + lane] : 0.f;
    float xv1 = (lane < 10) ? p.in[0][(size_t)(b0 + 1) * 10 + lane] : 0.f;
    h2u[lane] = dup2(smem[O_CLS + lane]);
#pragma unroll
    for (int i = 0; i < 10; i++) {
        float a = __shfl_sync(0xffffffffu, xv0, i);
        float b = __shfl_sync(0xffffffffu, xv1, i);
        u64 w  = dup2(smem[O_WFEAT + i * 32 + lane]);
        u64 bb = dup2(smem[O_BFEAT + i * 32 + lane]);
        h2u[(i + 1) * 32 + lane] = fma2(pack2(a, b), w, bb);
    }
    __syncwarp();

    block_pair(hoff, soff, lane);

    __syncthreads();
    stage_block(&smem[O_BLKW], &p.in[16], tid);
    __syncthreads();

    block2_pair(hoff, soff, lane);

    u64 v = mul2(h2u[lane], dup2(smem[O_CLFW + lane]));
#pragma unroll
    for (int mk = 16; mk; mk >>= 1) v = add2(v, shflx2(v, mk));
    if (valid && lane == 0) {
        float r0, r1; unpack2(v, r0, r1);
        float cb = smem[O_CLFB];
        *reinterpret_cast<float2*>(&p.out[b0]) = make_float2(r0 + cb, r1 + cb);
    }
}

extern "C" void kernel_launch(void* const* d_in, const int* in_sizes, int n_in,
                              void* d_out, int out_size)
{
    (void)in_sizes; (void)n_in; (void)out_size;
    KParams p;
    for (int i = 0; i < 30; i++) p.in[i] = (const float*)d_in[i];
    p.out = (float*)d_out;

    cudaFuncSetAttribute(tab_transformer_kernel,
                         cudaFuncAttributeMaxDynamicSharedMemorySize, SMEM_BYTES);

    const int grid = (NPAIR + NW - 1) / NW;   // 4096
    tab_transformer_kernel<<<grid, THREADS, SMEM_BYTES>>>(p);
}

// round 15
// speedup vs baseline: 1.6036x; 1.0002x over previous
#include <cuda_runtime.h>

// Fused 2-block tiny-transformer, 131072 sequences. One warp = TWO batches
// packed as f32x2. Block 1: full 11-token block; FFN2 split-half (SN<=6
// partial arrays — fits registers); out-proj UNSPLIT (S=11 partials spill).
// Block 2: CLS-specialized; V in registers; out-proj + FFN2 split-half with
// scalar partials.

namespace {
constexpr int S  = 11;
constexpr int NW = 16;
constexpr int THREADS = NW * 32;                  // 512
constexpr int BTOT = 131072;
constexpr int NPAIR = BTOT / 2;                   // 65536

// --- per-block weight layout (floats), output-major rows, stride%32==4 ------
constexpr int QKVW_STR = 36;
constexpr int OUTW_STR = 36;
constexpr int W1_STR   = 36;
constexpr int W2_STR   = 132;

constexpr int O_QKVW = 0;
constexpr int O_QKVB = O_QKVW + 96 * QKVW_STR;    // 3456
constexpr int O_OUTW = O_QKVB + 96;               // 3552
constexpr int O_OUTB = O_OUTW + 32 * OUTW_STR;    // 4704
constexpr int O_LNAG = O_OUTB + 32;
constexpr int O_LNAB = O_LNAG + 32;
constexpr int O_W1   = O_LNAB + 32;               // 4800
constexpr int O_B1   = O_W1 + 128 * W1_STR;       // 9408
constexpr int O_W2   = O_B1 + 128;                // 9536
constexpr int O_B2   = O_W2 + 32 * W2_STR;        // 13760
constexpr int O_LNBG = O_B2 + 32;
constexpr int O_LNBB = O_LNBG + 32;
constexpr int BLK_SZ = O_LNBB + 32;               // 13856

// --- global smem layout (floats) ---
constexpr int O_WFEAT = 0;
constexpr int O_BFEAT = O_WFEAT + 320;
constexpr int O_CLS   = O_BFEAT + 320;
constexpr int O_CLFW  = O_CLS + 32;
constexpr int O_CLFB  = O_CLFW + 32;
constexpr int O_BLKW  = 720;
constexpr int O_ACT   = O_BLKW + BLK_SZ;          // 14576

// per-warp activation region (floats)
constexpr int H2_F   = 12 * 32 * 2;               // h2 [12][32] float2 = 768
// block1 staging (float2 units): q[11][16], k[11][16], v[11][16], ctx[11][34]
constexpr int F2_QS  = 0;
constexpr int F2_KS  = 176;
constexpr int F2_VS  = 352;
constexpr int F2_CTX = 528;
constexpr int CTX_STR = 34;
constexpr int LN_MU  = 374;                       // mu/sig offset in LN buf
// block2 staging (float2 units): q0[32], k[11][32], ctx[32]
constexpr int F2_Q2  = 0;
constexpr int F2_K2  = 32;
constexpr int F2_C2  = 736;
constexpr int F2_G2  = 0;                         // ffn g buffer (reuse)
constexpr int STG_F2 = 928;
constexpr int ACT_F  = H2_F + STG_F2 * 2;         // 2624 floats / warp
constexpr int SMEM_FLOATS = O_ACT + NW * ACT_F;   // 56560
constexpr int SMEM_BYTES  = SMEM_FLOATS * 4;      // 226240
}

extern __shared__ float smem[];

using u64 = unsigned long long;

static __device__ __forceinline__ u64 pack2(float x, float y) {
    u64 r; asm("mov.b64 %0,{%1,%2};" : "=l"(r) : "f"(x), "f"(y)); return r;
}
static __device__ __forceinline__ void unpack2(u64 v, float& x, float& y) {
    asm("mov.b64 {%0,%1},%2;" : "=f"(x), "=f"(y) : "l"(v));
}
static __device__ __forceinline__ u64 dup2(float x) { return pack2(x, x); }
static __device__ __forceinline__ u64 fma2(u64 a, u64 b, u64 c) {
    u64 d; asm("fma.rn.f32x2 %0,%1,%2,%3;" : "=l"(d) : "l"(a), "l"(b), "l"(c)); return d;
}
static __device__ __forceinline__ u64 add2(u64 a, u64 b) {
    u64 d; asm("add.rn.f32x2 %0,%1,%2;" : "=l"(d) : "l"(a), "l"(b)); return d;
}
static __device__ __forceinline__ u64 mul2(u64 a, u64 b) {
    u64 d; asm("mul.rn.f32x2 %0,%1,%2;" : "=l"(d) : "l"(a), "l"(b)); return d;
}
static __device__ __forceinline__ u64 neg2(u64 x) {
    return x ^ 0x8000000080000000ULL;
}
static __device__ __forceinline__ u64 shflx2(u64 v, int m) {
    float x, y; unpack2(v, x, y);
    x = __shfl_xor_sync(0xffffffffu, x, m);
    y = __shfl_xor_sync(0xffffffffu, y, m);
    return pack2(x, y);
}
static __device__ __forceinline__ float gelu1(float x) {
    return 0.5f * x * (1.0f + erff(x * 0.7071067811865475f));
}
// single-token LN via butterfly (block 2)
static __device__ __forceinline__ u64 ln_norm(u64 v, u64 lg, u64 lb) {
    u64 sum = v, sq = mul2(v, v);
#pragma unroll
    for (int mk = 16; mk; mk >>= 1) {
        sum = add2(sum, shflx2(sum, mk));
        sq  = add2(sq,  shflx2(sq,  mk));
    }
    float s0, s1, q0, q1, v0, v1;
    unpack2(sum, s0, s1); unpack2(sq, q0, q1); unpack2(v, v0, v1);
    float mu0 = s0 * 0.03125f, mu1 = s1 * 0.03125f;
    float r0 = rsqrtf(fmaf(-mu0, mu0, q0 * 0.03125f) + 1e-5f);
    float r1 = rsqrtf(fmaf(-mu1, mu1, q1 * 0.03125f) + 1e-5f);
    return fma2(pack2((v0 - mu0) * r0, (v1 - mu1) * r1), lg, lb);
}

struct KParams {
    const float* in[30];
    float* out;
};

// Staged LayerNorm over SN tokens (block 1): stats by lane t, applied by all.
template <int SN>
static __device__ __forceinline__ void ln_apply(u64* h2u, int hbase, u64* buf,
                                                const u64* v, u64 lg, u64 lb,
                                                int lane)
{
#pragma unroll
    for (int t = 0; t < SN; t++) buf[t * 34 + lane] = v[t];
    __syncwarp();
    if (lane < SN) {
        const float2* row = reinterpret_cast<const float2*>(&buf[lane * 34]);
        u64 s = pack2(0.f, 0.f), q = pack2(0.f, 0.f);
#pragma unroll
        for (int i = 0; i < 16; i++) {
            float4 c = *reinterpret_cast<const float4*>(&row[i * 2]);
            u64 a = pack2(c.x, c.y), b = pack2(c.z, c.w);
            s = add2(s, add2(a, b));
            q = fma2(a, a, q); q = fma2(b, b, q);
        }
        float s0, s1, q0, q1;
        unpack2(s, s0, s1); unpack2(q, q0, q1);
        float mu0 = s0 * 0.03125f, mu1 = s1 * 0.03125f;
        float r0 = rsqrtf(fmaf(-mu0, mu0, q0 * 0.03125f) + 1e-5f);
        float r1 = rsqrtf(fmaf(-mu1, mu1, q1 * 0.03125f) + 1e-5f);
        *reinterpret_cast<float4*>(&buf[LN_MU + 2 * lane]) =
            make_float4(mu0, mu1, r0, r1);
    }
    __syncwarp();
#pragma unroll
    for (int t = 0; t < SN; t++) {
        float4 ms = *reinterpret_cast<const float4*>(&buf[LN_MU + 2 * t]);
        u64 mu = pack2(ms.x, ms.y), rs = pack2(ms.z, ms.w);
        u64 t1 = mul2(rs, lg);
        h2u[hbase + t * 32 + lane] = fma2(v[t], t1, add2(lb, neg2(mul2(mu, t1))));
    }
    __syncwarp();
}

// Stage one block's weights: straight strided float4 copies (output-major).
static __device__ __forceinline__ void stage_block(float* W, const float* const* q,
                                                   int tid)
{
    for (int i4 = tid; i4 < 768; i4 += THREADS) {         // qkv [96][32]
        float4 v = reinterpret_cast<const float4*>(q[0])[i4];
        int e = i4 >> 3, c = (i4 & 7) * 4;
        *reinterpret_cast<float4*>(&W[O_QKVW + e * QKVW_STR + c]) = v;
    }
    for (int i = tid; i < 96; i += THREADS) W[O_QKVB + i] = q[1][i];
    for (int i4 = tid; i4 < 256; i4 += THREADS) {         // out_w [32][32]
        float4 v = reinterpret_cast<const float4*>(q[2])[i4];
        int e = i4 >> 3, c = (i4 & 7) * 4;
        *reinterpret_cast<float4*>(&W[O_OUTW + e * OUTW_STR + c]) = v;
    }
    if (tid < 32) {
        W[O_OUTB + tid] = q[3][tid];
        W[O_LNAG + tid] = q[4][tid];
        W[O_LNAB + tid] = q[5][tid];
    }
    for (int i4 = tid; i4 < 1024; i4 += THREADS) {        // w1 [128][32]
        float4 v = reinterpret_cast<const float4*>(q[6])[i4];
        int f = i4 >> 3, c = (i4 & 7) * 4;
        *reinterpret_cast<float4*>(&W[O_W1 + f * W1_STR + c]) = v;
    }
    for (int i = tid; i < 128; i += THREADS) W[O_B1 + i] = q[7][i];
    for (int i4 = tid; i4 < 1024; i4 += THREADS) {        // w2 [32][128]
        float4 v = reinterpret_cast<const float4*>(q[8])[i4];
        int d = i4 >> 5, c = (i4 & 31) * 4;
        *reinterpret_cast<float4*>(&W[O_W2 + d * W2_STR + c]) = v;
    }
    if (tid < 32) {
        W[O_B2   + tid] = q[9][tid];
        W[O_LNBG + tid] = q[10][tid];
        W[O_LNBB + tid] = q[11][tid];
    }
}

// FFN over tokens [SB, SB+SN) (block 1): FFN1 -> GELU -> FFN2 split-half
// -> +res -> LN_B.
template <int SB, int SN>
static __device__ __forceinline__ void ffn_pass(u64* h2u, u64* g2u,
                                                const float* W, int lane)
{
    const float2* g2f = reinterpret_cast<const float2*>(g2u);
    const float2* h2f = reinterpret_cast<const float2*>(h2u);

    // ---- FFN1: 32 -> 128 ----
    u64 ga[4][SN];
#pragma unroll
    for (int j = 0; j < 4; j++) {
        u64 b = dup2(W[O_B1 + lane + 32 * j]);
#pragma unroll
        for (int t = 0; t < SN; t++) ga[j][t] = b;
    }
    for (int d0 = 0; d0 < 32; d0 += 4) {
        u64 w[4][4];
#pragma unroll
        for (int j = 0; j < 4; j++) {
            float4 f = *reinterpret_cast<const float4*>(
                &W[O_W1 + (lane + 32 * j) * W1_STR + d0]);
            w[j][0] = dup2(f.x); w[j][1] = dup2(f.y);
            w[j][2] = dup2(f.z); w[j][3] = dup2(f.w);
        }
#pragma unroll
        for (int t = 0; t < SN; t++) {
            float4 a = *reinterpret_cast<const float4*>(&h2f[(SB + t) * 32 + d0]);
            float4 b = *reinterpret_cast<const float4*>(&h2f[(SB + t) * 32 + d0 + 2]);
            u64 x[4] = {pack2(a.x, a.y), pack2(a.z, a.w),
                        pack2(b.x, b.y), pack2(b.z, b.w)};
#pragma unroll
            for (int j = 0; j < 4; j++)
#pragma unroll
                for (int m = 0; m < 4; m++)
                    ga[j][t] = fma2(x[m], w[j][m], ga[j][t]);
        }
    }
#pragma unroll
    for (int j = 0; j < 4; j++)
#pragma unroll
        for (int t = 0; t < SN; t++) {
            float a, b; unpack2(ga[j][t], a, b);
            g2u[t * 128 + lane + 32 * j] = pack2(gelu1(a), gelu1(b));
        }
    __syncwarp();

    // ---- FFN2: 128 -> 32, split-half across lane groups ----
    const int g  = lane >> 4;
    const int lg = lane & 15;
    u64 p0[SN], p1[SN];
#pragma unroll
    for (int t = 0; t < SN; t++) { p0[t] = 0ull; p1[t] = 0ull; }
    const float*  w2a = &W[O_W2 + lg * W2_STR + g * 64];
    const float*  w2b = &W[O_W2 + (lg + 16) * W2_STR + g * 64];
    const float2* gh  = &g2f[g * 64];            // f2 offset of this f-half
    for (int fo = 0; fo < 64; fo += 4) {
        float4 wa = *reinterpret_cast<const float4*>(&w2a[fo]);
        float4 wb = *reinterpret_cast<const float4*>(&w2b[fo]);
        u64 wa0 = dup2(wa.x), wa1 = dup2(wa.y), wa2 = dup2(wa.z), wa3 = dup2(wa.w);
        u64 wb0 = dup2(wb.x), wb1 = dup2(wb.y), wb2 = dup2(wb.z), wb3 = dup2(wb.w);
#pragma unroll
        for (int t = 0; t < SN; t++) {
            float4 a = *reinterpret_cast<const float4*>(&gh[t * 128 + fo]);
            float4 b = *reinterpret_cast<const float4*>(&gh[t * 128 + fo + 2]);
            u64 x0 = pack2(a.x, a.y), x1 = pack2(a.z, a.w);
            u64 x2 = pack2(b.x, b.y), x3 = pack2(b.z, b.w);
            p0[t] = fma2(x0, wa0, p0[t]); p0[t] = fma2(x1, wa1, p0[t]);
            p0[t] = fma2(x2, wa2, p0[t]); p0[t] = fma2(x3, wa3, p0[t]);
            p1[t] = fma2(x0, wb0, p1[t]); p1[t] = fma2(x1, wb1, p1[t]);
            p1[t] = fma2(x2, wb2, p1[t]); p1[t] = fma2(x3, wb3, p1[t]);
        }
    }
    u64 o2[SN];
    {
        u64 bias = dup2(W[O_B2 + lane]);
#pragma unroll
        for (int t = 0; t < SN; t++) {
            u64 r0 = add2(p0[t], shflx2(p0[t], 16));
            u64 r1 = add2(p1[t], shflx2(p1[t], 16));
            o2[t] = add2(add2((lane < 16) ? r0 : r1, bias),
                         h2u[(SB + t) * 32 + lane]);
        }
    }
    __syncwarp();
    ln_apply<SN>(h2u, SB * 32, g2u,
                 o2, dup2(W[O_LNBG + lane]), dup2(W[O_LNBB + lane]), lane);
}

// Block 1: full transformer block for a packed batch-pair.
__device__ __noinline__ void block_pair(int hoff, int soff, int lane)
{
    u64* h2u = reinterpret_cast<u64*>(&smem[hoff]);
    u64* stg = reinterpret_cast<u64*>(&smem[soff]);
    const float2* h2f = reinterpret_cast<const float2*>(h2u);
    const float2* stf = reinterpret_cast<const float2*>(stg);
    const float* W = &smem[O_BLKW];

    // ---------------- QKV projection (lane = output dim) ----------------
    u64 qa[S], ka[S], va[S];
    {
        u64 bq = dup2(W[O_QKVB + lane]);
        u64 bk = dup2(W[O_QKVB + 32 + lane]);
        u64 bv = dup2(W[O_QKVB + 64 + lane]);
#pragma unroll
        for (int s = 0; s < S; s++) { qa[s] = bq; ka[s] = bk; va[s] = bv; }
    }
    for (int d0 = 0; d0 < 32; d0 += 4) {
        float4 fq = *reinterpret_cast<const float4*>(&W[O_QKVW + lane * QKVW_STR + d0]);
        float4 fk = *reinterpret_cast<const float4*>(&W[O_QKVW + (lane + 32) * QKVW_STR + d0]);
        float4 fv = *reinterpret_cast<const float4*>(&W[O_QKVW + (lane + 64) * QKVW_STR + d0]);
        u64 wq[4] = {dup2(fq.x), dup2(fq.y), dup2(fq.z), dup2(fq.w)};
        u64 wk[4] = {dup2(fk.x), dup2(fk.y), dup2(fk.z), dup2(fk.w)};
        u64 wv[4] = {dup2(fv.x), dup2(fv.y), dup2(fv.z), dup2(fv.w)};
#pragma unroll
        for (int s = 0; s < S; s++) {
            float4 a = *reinterpret_cast<const float4*>(&h2f[s * 32 + d0]);
            float4 b = *reinterpret_cast<const float4*>(&h2f[s * 32 + d0 + 2]);
            u64 x[4] = {pack2(a.x, a.y), pack2(a.z, a.w),
                        pack2(b.x, b.y), pack2(b.z, b.w)};
#pragma unroll
            for (int j = 0; j < 4; j++) {
                qa[s] = fma2(x[j], wq[j], qa[s]);
                ka[s] = fma2(x[j], wk[j], ka[s]);
                va[s] = fma2(x[j], wv[j], va[s]);
            }
        }
    }
    {
        u64 scl = dup2(0.35355339059327373f);
#pragma unroll
        for (int s = 0; s < S; s++) qa[s] = mul2(qa[s], scl);
    }

    // ---------------- attention: two head-pair passes, shuffle-free ---------
    const int qi = (lane >> 1) > 10 ? 10 : (lane >> 1);
    const int hl = lane & 1;
    const int hb = hl * 8;
#pragma unroll
    for (int p = 0; p < 2; p++) {
        if ((lane >> 4) == p) {
            int ld = lane & 15;
#pragma unroll
            for (int s = 0; s < S; s++) {
                stg[F2_QS + s * 16 + ld] = qa[s];
                stg[F2_KS + s * 16 + ld] = ka[s];
                stg[F2_VS + s * 16 + ld] = va[s];
            }
        }
        __syncwarp();

        u64 qr[8];
#pragma unroll
        for (int j = 0; j < 8; j += 2) {
            float4 t = *reinterpret_cast<const float4*>(&stf[F2_QS + qi * 16 + hb + j]);
            qr[j] = pack2(t.x, t.y); qr[j + 1] = pack2(t.z, t.w);
        }
        float e0[S], e1[S];
#pragma unroll
        for (int ki = 0; ki < S; ki++) {
            u64 acc = pack2(0.f, 0.f);
#pragma unroll
            for (int j = 0; j < 8; j += 2) {
                float4 kv = *reinterpret_cast<const float4*>(&stf[F2_KS + ki * 16 + hb + j]);
                acc = fma2(qr[j],     pack2(kv.x, kv.y), acc);
                acc = fma2(qr[j + 1], pack2(kv.z, kv.w), acc);
            }
            unpack2(acc, e0[ki], e1[ki]);
        }
        float m0 = e0[0], m1 = e1[0];
#pragma unroll
        for (int ki = 1; ki < S; ki++) { m0 = fmaxf(m0, e0[ki]); m1 = fmaxf(m1, e1[ki]); }
        float den0 = 0.f, den1 = 0.f;
#pragma unroll
        for (int ki = 0; ki < S; ki++) {
            e0[ki] = __expf(e0[ki] - m0); den0 += e0[ki];
            e1[ki] = __expf(e1[ki] - m1); den1 += e1[ki];
        }
        u64 cacc[8];
#pragma unroll
        for (int j = 0; j < 8; j++) cacc[j] = pack2(0.f, 0.f);
#pragma unroll
        for (int ki = 0; ki < S; ki++) {
            u64 ev = pack2(e0[ki], e1[ki]);
#pragma unroll
            for (int j = 0; j < 8; j += 2) {
                float4 vv = *reinterpret_cast<const float4*>(&stf[F2_VS + ki * 16 + hb + j]);
                cacc[j]     = fma2(ev, pack2(vv.x, vv.y), cacc[j]);
                cacc[j + 1] = fma2(ev, pack2(vv.z, vv.w), cacc[j + 1]);
            }
        }
        if (lane < 22) {
            u64 inv = pack2(1.0f / den0, 1.0f / den1);
            int cb = F2_CTX + qi * CTX_STR + (p * 2 + hl) * 8;
#pragma unroll
            for (int j = 0; j < 8; j++) stg[cb + j] = mul2(cacc[j], inv);
        }
        __syncwarp();
    }

    // ---------------- output projection + residual + LN_A (unsplit) ---------
    u64 o[S];
    {
        u64 bo = dup2(W[O_OUTB + lane]);
#pragma unroll
        for (int s = 0; s < S; s++) o[s] = bo;
    }
    for (int d0 = 0; d0 < 32; d0 += 4) {
        float4 fw = *reinterpret_cast<const float4*>(&W[O_OUTW + lane * OUTW_STR + d0]);
        u64 w0 = dup2(fw.x), w1 = dup2(fw.y), w2 = dup2(fw.z), w3 = dup2(fw.w);
#pragma unroll
        for (int s = 0; s < S; s++) {
            float4 c0 = *reinterpret_cast<const float4*>(&stf[F2_CTX + s * CTX_STR + d0]);
            float4 c1 = *reinterpret_cast<const float4*>(&stf[F2_CTX + s * CTX_STR + d0 + 2]);
            o[s] = fma2(pack2(c0.x, c0.y), w0, o[s]);
            o[s] = fma2(pack2(c0.z, c0.w), w1, o[s]);
            o[s] = fma2(pack2(c1.x, c1.y), w2, o[s]);
            o[s] = fma2(pack2(c1.z, c1.w), w3, o[s]);
        }
    }
#pragma unroll
    for (int s = 0; s < S; s++)
        o[s] = add2(o[s], h2u[s * 32 + lane]);
    __syncwarp();
    ln_apply<S>(h2u, 0, stg + F2_CTX,
                o, dup2(W[O_LNAG + lane]), dup2(W[O_LNAB + lane]), lane);

    ffn_pass<0, 6>(h2u, stg, W, lane);
    ffn_pass<6, 5>(h2u, stg, W, lane);
}

// Block 2: CLS-specialized — K/V for all tokens; V stays in registers.
// Out-proj and FFN2 split-half with scalar partials (no register pressure).
__device__ __noinline__ void block2_pair(int hoff, int soff, int lane)
{
    u64* h2u = reinterpret_cast<u64*>(&smem[hoff]);
    u64* stg = reinterpret_cast<u64*>(&smem[soff]);
    const float2* h2f = reinterpret_cast<const float2*>(h2u);
    const float2* stf = reinterpret_cast<const float2*>(stg);
    const float* W = &smem[O_BLKW];

    // ---------------- QKV: k,v all tokens; q token 0 only -------------------
    u64 ka[S], va[S];
    u64 q0 = dup2(W[O_QKVB + lane]);
    {
        u64 bk = dup2(W[O_QKVB + 32 + lane]);
        u64 bv = dup2(W[O_QKVB + 64 + lane]);
#pragma unroll
        for (int s = 0; s < S; s++) { ka[s] = bk; va[s] = bv; }
    }
    for (int d0 = 0; d0 < 32; d0 += 4) {
        float4 fq = *reinterpret_cast<const float4*>(&W[O_QKVW + lane * QKVW_STR + d0]);
        float4 fk = *reinterpret_cast<const float4*>(&W[O_QKVW + (lane + 32) * QKVW_STR + d0]);
        float4 fv = *reinterpret_cast<const float4*>(&W[O_QKVW + (lane + 64) * QKVW_STR + d0]);
        u64 wq[4] = {dup2(fq.x), dup2(fq.y), dup2(fq.z), dup2(fq.w)};
        u64 wk[4] = {dup2(fk.x), dup2(fk.y), dup2(fk.z), dup2(fk.w)};
        u64 wv[4] = {dup2(fv.x), dup2(fv.y), dup2(fv.z), dup2(fv.w)};
#pragma unroll
        for (int s = 0; s < S; s++) {
            float4 a = *reinterpret_cast<const float4*>(&h2f[s * 32 + d0]);
            float4 b = *reinterpret_cast<const float4*>(&h2f[s * 32 + d0 + 2]);
            u64 x[4] = {pack2(a.x, a.y), pack2(a.z, a.w),
                        pack2(b.x, b.y), pack2(b.z, b.w)};
#pragma unroll
            for (int j = 0; j < 4; j++) {
                ka[s] = fma2(x[j], wk[j], ka[s]);
                va[s] = fma2(x[j], wv[j], va[s]);
            }
            if (s == 0) {
#pragma unroll
                for (int j = 0; j < 4; j++) q0 = fma2(x[j], wq[j], q0);
            }
        }
    }
    q0 = mul2(q0, dup2(0.35355339059327373f));

    // stage q0 / K only (lane = dim); V stays in registers
    stg[F2_Q2 + lane] = q0;
#pragma unroll
    for (int s = 0; s < S; s++)
        stg[F2_K2 + s * 32 + lane] = ka[s];
    __syncwarp();

    // ---------------- attention row 0: lane = dim, head = lane>>3 -----------
    const int hb2 = (lane >> 3) * 8;
    u64 qr[8];
#pragma unroll
    for (int j = 0; j < 8; j += 2) {
        float4 t = *reinterpret_cast<const float4*>(&stf[F2_Q2 + hb2 + j]);
        qr[j] = pack2(t.x, t.y); qr[j + 1] = pack2(t.z, t.w);
    }
    float e0[S], e1[S];
#pragma unroll
    for (int ki = 0; ki < S; ki++) {
        u64 acc = pack2(0.f, 0.f);
#pragma unroll
        for (int j = 0; j < 8; j += 2) {
            float4 kv = *reinterpret_cast<const float4*>(&stf[F2_K2 + ki * 32 + hb2 + j]);
            acc = fma2(qr[j],     pack2(kv.x, kv.y), acc);
            acc = fma2(qr[j + 1], pack2(kv.z, kv.w), acc);
        }
        unpack2(acc, e0[ki], e1[ki]);
    }
    float m0 = e0[0], m1 = e1[0];
#pragma unroll
    for (int ki = 1; ki < S; ki++) { m0 = fmaxf(m0, e0[ki]); m1 = fmaxf(m1, e1[ki]); }
    float den0 = 0.f, den1 = 0.f;
#pragma unroll
    for (int ki = 0; ki < S; ki++) {
        e0[ki] = __expf(e0[ki] - m0); den0 += e0[ki];
        e1[ki] = __expf(e1[ki] - m1); den1 += e1[ki];
    }
    u64 c = pack2(0.f, 0.f);
#pragma unroll
    for (int ki = 0; ki < S; ki++)
        c = fma2(pack2(e0[ki], e1[ki]), va[ki], c);    // V from registers
    c = mul2(c, pack2(1.0f / den0, 1.0f / den1));
    stg[F2_C2 + lane] = c;
    __syncwarp();

    // ------------- out-proj token 0 (split-half, scalar partials) -----------
    u64 hn;
    {
        const int g  = lane >> 4;
        const int lg = lane & 15;
        u64 p0 = 0ull, p1 = 0ull;
        const float* owa = &W[O_OUTW + lg * OUTW_STR + g * 16];
        const float* owb = &W[O_OUTW + (lg + 16) * OUTW_STR + g * 16];
        for (int dd = 0; dd < 16; dd += 4) {
            float4 wa = *reinterpret_cast<const float4*>(&owa[dd]);
            float4 wb = *reinterpret_cast<const float4*>(&owb[dd]);
            float4 c0 = *reinterpret_cast<const float4*>(&stf[F2_C2 + g * 16 + dd]);
            float4 c1 = *reinterpret_cast<const float4*>(&stf[F2_C2 + g * 16 + dd + 2]);
            u64 x0 = pack2(c0.x, c0.y), x1 = pack2(c0.z, c0.w);
            u64 x2 = pack2(c1.x, c1.y), x3 = pack2(c1.z, c1.w);
            p0 = fma2(x0, dup2(wa.x), p0); p0 = fma2(x1, dup2(wa.y), p0);
            p0 = fma2(x2, dup2(wa.z), p0); p0 = fma2(x3, dup2(wa.w), p0);
            p1 = fma2(x0, dup2(wb.x), p1); p1 = fma2(x1, dup2(wb.y), p1);
            p1 = fma2(x2, dup2(wb.z), p1); p1 = fma2(x3, dup2(wb.w), p1);
        }
        u64 r0 = add2(p0, shflx2(p0, 16));
        u64 r1 = add2(p1, shflx2(p1, 16));
        u64 o = add2(add2((lane < 16) ? r0 : r1, dup2(W[O_OUTB + lane])),
                     h2u[lane]);
        hn = ln_norm(o, dup2(W[O_LNAG + lane]), dup2(W[O_LNAB + lane]));
        h2u[lane] = hn;
    }
    __syncwarp();

    // ---------------- FFN token 0 -------------------------------------------
    u64 ga[4];
#pragma unroll
    for (int j = 0; j < 4; j++) ga[j] = dup2(W[O_B1 + lane + 32 * j]);
    for (int d0 = 0; d0 < 32; d0 += 4) {
        float4 a = *reinterpret_cast<const float4*>(&h2f[d0]);
        float4 b = *reinterpret_cast<const float4*>(&h2f[d0 + 2]);
        u64 x[4] = {pack2(a.x, a.y), pack2(a.z, a.w),
                    pack2(b.x, b.y), pack2(b.z, b.w)};
#pragma unroll
        for (int j = 0; j < 4; j++) {
            float4 f = *reinterpret_cast<const float4*>(
                &W[O_W1 + (lane + 32 * j) * W1_STR + d0]);
            ga[j] = fma2(x[0], dup2(f.x), ga[j]);
            ga[j] = fma2(x[1], dup2(f.y), ga[j]);
            ga[j] = fma2(x[2], dup2(f.z), ga[j]);
            ga[j] = fma2(x[3], dup2(f.w), ga[j]);
        }
    }
#pragma unroll
    for (int j = 0; j < 4; j++) {
        float a, b; unpack2(ga[j], a, b);
        stg[F2_G2 + lane + 32 * j] = pack2(gelu1(a), gelu1(b));
    }
    __syncwarp();

    // ---- FFN2 token 0, split-half (scalar partials) ----
    {
        const int g  = lane >> 4;
        const int lg = lane & 15;
        u64 p0 = 0ull, p1 = 0ull;
        const float*  w2a = &W[O_W2 + lg * W2_STR + g * 64];
        const float*  w2b = &W[O_W2 + (lg + 16) * W2_STR + g * 64];
        const float2* gh  = &stf[F2_G2 + g * 64];
        for (int fo = 0; fo < 64; fo += 4) {
            float4 wa = *reinterpret_cast<const float4*>(&w2a[fo]);
            float4 wb = *reinterpret_cast<const float4*>(&w2b[fo]);
            float4 a = *reinterpret_cast<const float4*>(&gh[fo]);
            float4 b = *reinterpret_cast<const float4*>(&gh[fo + 2]);
            u64 x0 = pack2(a.x, a.y), x1 = pack2(a.z, a.w);
            u64 x2 = pack2(b.x, b.y), x3 = pack2(b.z, b.w);
            p0 = fma2(x0, dup2(wa.x), p0); p0 = fma2(x1, dup2(wa.y), p0);
            p0 = fma2(x2, dup2(wa.z), p0); p0 = fma2(x3, dup2(wa.w), p0);
            p1 = fma2(x0, dup2(wb.x), p1); p1 = fma2(x1, dup2(wb.y), p1);
            p1 = fma2(x2, dup2(wb.z), p1); p1 = fma2(x3, dup2(wb.w), p1);
        }
        u64 r0 = add2(p0, shflx2(p0, 16));
        u64 r1 = add2(p1, shflx2(p1, 16));
        u64 o2 = add2(add2((lane < 16) ? r0 : r1, dup2(W[O_B2 + lane])), hn);
        h2u[lane] = ln_norm(o2, dup2(W[O_LNBG + lane]), dup2(W[O_LNBB + lane]));
    }
    __syncwarp();
}

__global__ void __launch_bounds__(THREADS)
tab_transformer_kernel(KParams p)
{
    const int tid = threadIdx.x;

    for (int i = tid; i < 320; i += THREADS) smem[O_WFEAT + i] = p.in[1][i];
    for (int i = tid; i < 320; i += THREADS) smem[O_BFEAT + i] = p.in[2][i];
    if (tid < 32) {
        smem[O_CLS  + tid] = p.in[3][tid];
        smem[O_CLFW + tid] = p.in[28][tid];
    }
    if (tid == 0) smem[O_CLFB] = p.in[29][0];
    stage_block(&smem[O_BLKW], &p.in[4], tid);
    __syncthreads();

    const int warp = tid >> 5, lane = tid & 31;
    int pr = blockIdx.x * NW + warp;
    const bool valid = (pr < NPAIR);
    if (!valid) pr = NPAIR - 1;
    const int b0 = pr * 2;

    const int hoff = O_ACT + warp * ACT_F;
    const int soff = hoff + H2_F;
    u64* h2u = reinterpret_cast<u64*>(&smem[hoff]);

    float xv0 = (lane < 10) ? p.in[0][(size_t)b0 * 10 + lane] : 0.f;
    float xv1 = (lane < 10) ? p.in[0][(size_t)(b0 + 1) * 10 + lane] : 0.f;
    h2u[lane] = dup2(smem[O_CLS + lane]);
#pragma unroll
    for (int i = 0; i < 10; i++) {
        float a = __shfl_sync(0xffffffffu, xv0, i);
        float b = __shfl_sync(0xffffffffu, xv1, i);
        u64 w  = dup2(smem[O_WFEAT + i * 32 + lane]);
        u64 bb = dup2(smem[O_BFEAT + i * 32 + lane]);
        h2u[(i + 1) * 32 + lane] = fma2(pack2(a, b), w, bb);
    }
    __syncwarp();

    block_pair(hoff, soff, lane);

    __syncthreads();
    stage_block(&smem[O_BLKW], &p.in[16], tid);
    __syncthreads();

    block2_pair(hoff, soff, lane);

    u64 v = mul2(h2u[lane], dup2(smem[O_CLFW + lane]));
#pragma unroll
    for (int mk = 16; mk; mk >>= 1) v = add2(v, shflx2(v, mk));
    if (valid && lane == 0) {
        float r0, r1; unpack2(v, r0, r1);
        float cb = smem[O_CLFB];
        *reinterpret_cast<float2*>(&p.out[b0]) = make_float2(r0 + cb, r1 + cb);
    }
}

extern "C" void kernel_launch(void* const* d_in, const int* in_sizes, int n_in,
                              void* d_out, int out_size)
{
    (void)in_sizes; (void)n_in; (void)out_size;
    KParams p;
    for (int i = 0; i < 30; i++) p.in[i] = (const float*)d_in[i];
    p.out = (float*)d_out;

    cudaFuncSetAttribute(tab_transformer_kernel,
                         cudaFuncAttributeMaxDynamicSharedMemorySize, SMEM_BYTES);

    const int grid = (NPAIR + NW - 1) / NW;   // 4096
    tab_transformer_kernel<<<grid, THREADS, SMEM_BYTES>>>(p);
}

// round 16
// speedup vs baseline: 1.6052x; 1.0010x over previous
#include <cuda_runtime.h>

// Fused 2-block tiny-transformer, 131072 sequences. One warp = TWO batches
// packed as f32x2. Block 1: full 11-token block; FFN2 split-half (SN<=6
// partial arrays — fits registers); out-proj UNSPLIT (S=11 partials spill).
// Block 2: CLS-specialized; V in registers; out-proj + FFN2 split-half with
// scalar partials.

namespace {
constexpr int S  = 11;
constexpr int NW = 16;
constexpr int THREADS = NW * 32;                  // 512
constexpr int BTOT = 131072;
constexpr int NPAIR = BTOT / 2;                   // 65536

// --- per-block weight layout (floats), output-major rows, stride%32==4 ------
constexpr int QKVW_STR = 36;
constexpr int OUTW_STR = 36;
constexpr int W1_STR   = 36;
constexpr int W2_STR   = 132;

constexpr int O_QKVW = 0;
constexpr int O_QKVB = O_QKVW + 96 * QKVW_STR;    // 3456
constexpr int O_OUTW = O_QKVB + 96;               // 3552
constexpr int O_OUTB = O_OUTW + 32 * OUTW_STR;    // 4704
constexpr int O_LNAG = O_OUTB + 32;
constexpr int O_LNAB = O_LNAG + 32;
constexpr int O_W1   = O_LNAB + 32;               // 4800
constexpr int O_B1   = O_W1 + 128 * W1_STR;       // 9408
constexpr int O_W2   = O_B1 + 128;                // 9536
constexpr int O_B2   = O_W2 + 32 * W2_STR;        // 13760
constexpr int O_LNBG = O_B2 + 32;
constexpr int O_LNBB = O_LNBG + 32;
constexpr int BLK_SZ = O_LNBB + 32;               // 13856

// --- global smem layout (floats) ---
constexpr int O_WFEAT = 0;
constexpr int O_BFEAT = O_WFEAT + 320;
constexpr int O_CLS   = O_BFEAT + 320;
constexpr int O_CLFW  = O_CLS + 32;
constexpr int O_CLFB  = O_CLFW + 32;
constexpr int O_BLKW  = 720;
constexpr int O_ACT   = O_BLKW + BLK_SZ;          // 14576

// per-warp activation region (floats)
constexpr int H2_F   = 12 * 32 * 2;               // h2 [12][32] float2 = 768
// block1 staging (float2 units): q[11][16], k[11][16], v[11][16], ctx[11][34]
constexpr int F2_QS  = 0;
constexpr int F2_KS  = 176;
constexpr int F2_VS  = 352;
constexpr int F2_CTX = 528;
constexpr int CTX_STR = 34;
constexpr int LN_MU  = 374;                       // mu/sig offset in LN buf
// block2 staging (float2 units): q0[32], k[11][32], ctx[32]
constexpr int F2_Q2  = 0;
constexpr int F2_K2  = 32;
constexpr int F2_C2  = 736;
constexpr int F2_G2  = 0;                         // ffn g buffer (reuse)
constexpr int STG_F2 = 928;
constexpr int ACT_F  = H2_F + STG_F2 * 2;         // 2624 floats / warp
constexpr int SMEM_FLOATS = O_ACT + NW * ACT_F;   // 56560
constexpr int SMEM_BYTES  = SMEM_FLOATS * 4;      // 226240
}

extern __shared__ float smem[];

using u64 = unsigned long long;

static __device__ __forceinline__ u64 pack2(float x, float y) {
    u64 r; asm("mov.b64 %0,{%1,%2};" : "=l"(r) : "f"(x), "f"(y)); return r;
}
static __device__ __forceinline__ void unpack2(u64 v, float& x, float& y) {
    asm("mov.b64 {%0,%1},%2;" : "=f"(x), "=f"(y) : "l"(v));
}
static __device__ __forceinline__ u64 dup2(float x) { return pack2(x, x); }
static __device__ __forceinline__ u64 fma2(u64 a, u64 b, u64 c) {
    u64 d; asm("fma.rn.f32x2 %0,%1,%2,%3;" : "=l"(d) : "l"(a), "l"(b), "l"(c)); return d;
}
static __device__ __forceinline__ u64 add2(u64 a, u64 b) {
    u64 d; asm("add.rn.f32x2 %0,%1,%2;" : "=l"(d) : "l"(a), "l"(b)); return d;
}
static __device__ __forceinline__ u64 mul2(u64 a, u64 b) {
    u64 d; asm("mul.rn.f32x2 %0,%1,%2;" : "=l"(d) : "l"(a), "l"(b)); return d;
}
static __device__ __forceinline__ u64 neg2(u64 x) {
    return x ^ 0x8000000080000000ULL;
}
static __device__ __forceinline__ u64 shflx2(u64 v, int m) {
    float x, y; unpack2(v, x, y);
    x = __shfl_xor_sync(0xffffffffu, x, m);
    y = __shfl_xor_sync(0xffffffffu, y, m);
    return pack2(x, y);
}
static __device__ __forceinline__ float gelu1(float x) {
    return 0.5f * x * (1.0f + erff(x * 0.7071067811865475f));
}
// single-token LN via butterfly (block 2)
static __device__ __forceinline__ u64 ln_norm(u64 v, u64 lg, u64 lb) {
    u64 sum = v, sq = mul2(v, v);
#pragma unroll
    for (int mk = 16; mk; mk >>= 1) {
        sum = add2(sum, shflx2(sum, mk));
        sq  = add2(sq,  shflx2(sq,  mk));
    }
    float s0, s1, q0, q1, v0, v1;
    unpack2(sum, s0, s1); unpack2(sq, q0, q1); unpack2(v, v0, v1);
    float mu0 = s0 * 0.03125f, mu1 = s1 * 0.03125f;
    float r0 = rsqrtf(fmaf(-mu0, mu0, q0 * 0.03125f) + 1e-5f);
    float r1 = rsqrtf(fmaf(-mu1, mu1, q1 * 0.03125f) + 1e-5f);
    return fma2(pack2((v0 - mu0) * r0, (v1 - mu1) * r1), lg, lb);
}

struct KParams {
    const float* in[30];
    float* out;
};

// Staged LayerNorm over SN tokens (block 1): stats by lane t, applied by all.
template <int SN>
static __device__ __forceinline__ void ln_apply(u64* h2u, int hbase, u64* buf,
                                                const u64* v, u64 lg, u64 lb,
                                                int lane)
{
#pragma unroll
    for (int t = 0; t < SN; t++) buf[t * 34 + lane] = v[t];
    __syncwarp();
    if (lane < SN) {
        const float2* row = reinterpret_cast<const float2*>(&buf[lane * 34]);
        u64 s = pack2(0.f, 0.f), q = pack2(0.f, 0.f);
#pragma unroll
        for (int i = 0; i < 16; i++) {
            float4 c = *reinterpret_cast<const float4*>(&row[i * 2]);
            u64 a = pack2(c.x, c.y), b = pack2(c.z, c.w);
            s = add2(s, add2(a, b));
            q = fma2(a, a, q); q = fma2(b, b, q);
        }
        float s0, s1, q0, q1;
        unpack2(s, s0, s1); unpack2(q, q0, q1);
        float mu0 = s0 * 0.03125f, mu1 = s1 * 0.03125f;
        float r0 = rsqrtf(fmaf(-mu0, mu0, q0 * 0.03125f) + 1e-5f);
        float r1 = rsqrtf(fmaf(-mu1, mu1, q1 * 0.03125f) + 1e-5f);
        *reinterpret_cast<float4*>(&buf[LN_MU + 2 * lane]) =
            make_float4(mu0, mu1, r0, r1);
    }
    __syncwarp();
#pragma unroll
    for (int t = 0; t < SN; t++) {
        float4 ms = *reinterpret_cast<const float4*>(&buf[LN_MU + 2 * t]);
        u64 mu = pack2(ms.x, ms.y), rs = pack2(ms.z, ms.w);
        u64 t1 = mul2(rs, lg);
        h2u[hbase + t * 32 + lane] = fma2(v[t], t1, add2(lb, neg2(mul2(mu, t1))));
    }
    __syncwarp();
}

// Stage one block's weights: straight strided float4 copies (output-major).
static __device__ __forceinline__ void stage_block(float* W, const float* const* q,
                                                   int tid)
{
    for (int i4 = tid; i4 < 768; i4 += THREADS) {         // qkv [96][32]
        float4 v = reinterpret_cast<const float4*>(q[0])[i4];
        int e = i4 >> 3, c = (i4 & 7) * 4;
        *reinterpret_cast<float4*>(&W[O_QKVW + e * QKVW_STR + c]) = v;
    }
    for (int i = tid; i < 96; i += THREADS) W[O_QKVB + i] = q[1][i];
    for (int i4 = tid; i4 < 256; i4 += THREADS) {         // out_w [32][32]
        float4 v = reinterpret_cast<const float4*>(q[2])[i4];
        int e = i4 >> 3, c = (i4 & 7) * 4;
        *reinterpret_cast<float4*>(&W[O_OUTW + e * OUTW_STR + c]) = v;
    }
    if (tid < 32) {
        W[O_OUTB + tid] = q[3][tid];
        W[O_LNAG + tid] = q[4][tid];
        W[O_LNAB + tid] = q[5][tid];
    }
    for (int i4 = tid; i4 < 1024; i4 += THREADS) {        // w1 [128][32]
        float4 v = reinterpret_cast<const float4*>(q[6])[i4];
        int f = i4 >> 3, c = (i4 & 7) * 4;
        *reinterpret_cast<float4*>(&W[O_W1 + f * W1_STR + c]) = v;
    }
    for (int i = tid; i < 128; i += THREADS) W[O_B1 + i] = q[7][i];
    for (int i4 = tid; i4 < 1024; i4 += THREADS) {        // w2 [32][128]
        float4 v = reinterpret_cast<const float4*>(q[8])[i4];
        int d = i4 >> 5, c = (i4 & 31) * 4;
        *reinterpret_cast<float4*>(&W[O_W2 + d * W2_STR + c]) = v;
    }
    if (tid < 32) {
        W[O_B2   + tid] = q[9][tid];
        W[O_LNBG + tid] = q[10][tid];
        W[O_LNBB + tid] = q[11][tid];
    }
}

// FFN over tokens [SB, SB+SN) (block 1): FFN1 -> GELU -> FFN2 split-half
// -> +res -> LN_B.
template <int SB, int SN>
static __device__ __forceinline__ void ffn_pass(u64* h2u, u64* g2u,
                                                const float* W, int lane)
{
    const float2* g2f = reinterpret_cast<const float2*>(g2u);
    const float2* h2f = reinterpret_cast<const float2*>(h2u);

    // ---- FFN1: 32 -> 128 ----
    u64 ga[4][SN];
#pragma unroll
    for (int j = 0; j < 4; j++) {
        u64 b = dup2(W[O_B1 + lane + 32 * j]);
#pragma unroll
        for (int t = 0; t < SN; t++) ga[j][t] = b;
    }
    for (int d0 = 0; d0 < 32; d0 += 4) {
        u64 w[4][4];
#pragma unroll
        for (int j = 0; j < 4; j++) {
            float4 f = *reinterpret_cast<const float4*>(
                &W[O_W1 + (lane + 32 * j) * W1_STR + d0]);
            w[j][0] = dup2(f.x); w[j][1] = dup2(f.y);
            w[j][2] = dup2(f.z); w[j][3] = dup2(f.w);
        }
#pragma unroll
        for (int t = 0; t < SN; t++) {
            float4 a = *reinterpret_cast<const float4*>(&h2f[(SB + t) * 32 + d0]);
            float4 b = *reinterpret_cast<const float4*>(&h2f[(SB + t) * 32 + d0 + 2]);
            u64 x[4] = {pack2(a.x, a.y), pack2(a.z, a.w),
                        pack2(b.x, b.y), pack2(b.z, b.w)};
#pragma unroll
            for (int j = 0; j < 4; j++)
#pragma unroll
                for (int m = 0; m < 4; m++)
                    ga[j][t] = fma2(x[m], w[j][m], ga[j][t]);
        }
    }
#pragma unroll
    for (int j = 0; j < 4; j++)
#pragma unroll
        for (int t = 0; t < SN; t++) {
            float a, b; unpack2(ga[j][t], a, b);
            g2u[t * 128 + lane + 32 * j] = pack2(gelu1(a), gelu1(b));
        }
    __syncwarp();

    // ---- FFN2: 128 -> 32, split-half across lane groups ----
    const int g  = lane >> 4;
    const int lg = lane & 15;
    u64 p0[SN], p1[SN];
#pragma unroll
    for (int t = 0; t < SN; t++) { p0[t] = 0ull; p1[t] = 0ull; }
    const float*  w2a = &W[O_W2 + lg * W2_STR + g * 64];
    const float*  w2b = &W[O_W2 + (lg + 16) * W2_STR + g * 64];
    const float2* gh  = &g2f[g * 64];            // f2 offset of this f-half
    for (int fo = 0; fo < 64; fo += 4) {
        float4 wa = *reinterpret_cast<const float4*>(&w2a[fo]);
        float4 wb = *reinterpret_cast<const float4*>(&w2b[fo]);
        u64 wa0 = dup2(wa.x), wa1 = dup2(wa.y), wa2 = dup2(wa.z), wa3 = dup2(wa.w);
        u64 wb0 = dup2(wb.x), wb1 = dup2(wb.y), wb2 = dup2(wb.z), wb3 = dup2(wb.w);
#pragma unroll
        for (int t = 0; t < SN; t++) {
            float4 a = *reinterpret_cast<const float4*>(&gh[t * 128 + fo]);
            float4 b = *reinterpret_cast<const float4*>(&gh[t * 128 + fo + 2]);
            u64 x0 = pack2(a.x, a.y), x1 = pack2(a.z, a.w);
            u64 x2 = pack2(b.x, b.y), x3 = pack2(b.z, b.w);
            p0[t] = fma2(x0, wa0, p0[t]); p0[t] = fma2(x1, wa1, p0[t]);
            p0[t] = fma2(x2, wa2, p0[t]); p0[t] = fma2(x3, wa3, p0[t]);
            p1[t] = fma2(x0, wb0, p1[t]); p1[t] = fma2(x1, wb1, p1[t]);
            p1[t] = fma2(x2, wb2, p1[t]); p1[t] = fma2(x3, wb3, p1[t]);
        }
    }
    u64 o2[SN];
    {
        u64 bias = dup2(W[O_B2 + lane]);
#pragma unroll
        for (int t = 0; t < SN; t++) {
            u64 r0 = add2(p0[t], shflx2(p0[t], 16));
            u64 r1 = add2(p1[t], shflx2(p1[t], 16));
            o2[t] = add2(add2((lane < 16) ? r0 : r1, bias),
                         h2u[(SB + t) * 32 + lane]);
        }
    }
    __syncwarp();
    ln_apply<SN>(h2u, SB * 32, g2u,
                 o2, dup2(W[O_LNBG + lane]), dup2(W[O_LNBB + lane]), lane);
}

// Block 1: full transformer block for a packed batch-pair.
__device__ __noinline__ void block_pair(int hoff, int soff, int lane)
{
    u64* h2u = reinterpret_cast<u64*>(&smem[hoff]);
    u64* stg = reinterpret_cast<u64*>(&smem[soff]);
    const float2* h2f = reinterpret_cast<const float2*>(h2u);
    const float2* stf = reinterpret_cast<const float2*>(stg);
    const float* W = &smem[O_BLKW];

    // ---------------- QKV projection (lane = output dim) ----------------
    u64 qa[S], ka[S], va[S];
    {
        u64 bq = dup2(W[O_QKVB + lane]);
        u64 bk = dup2(W[O_QKVB + 32 + lane]);
        u64 bv = dup2(W[O_QKVB + 64 + lane]);
#pragma unroll
        for (int s = 0; s < S; s++) { qa[s] = bq; ka[s] = bk; va[s] = bv; }
    }
    for (int d0 = 0; d0 < 32; d0 += 4) {
        float4 fq = *reinterpret_cast<const float4*>(&W[O_QKVW + lane * QKVW_STR + d0]);
        float4 fk = *reinterpret_cast<const float4*>(&W[O_QKVW + (lane + 32) * QKVW_STR + d0]);
        float4 fv = *reinterpret_cast<const float4*>(&W[O_QKVW + (lane + 64) * QKVW_STR + d0]);
        u64 wq[4] = {dup2(fq.x), dup2(fq.y), dup2(fq.z), dup2(fq.w)};
        u64 wk[4] = {dup2(fk.x), dup2(fk.y), dup2(fk.z), dup2(fk.w)};
        u64 wv[4] = {dup2(fv.x), dup2(fv.y), dup2(fv.z), dup2(fv.w)};
#pragma unroll
        for (int s = 0; s < S; s++) {
            float4 a = *reinterpret_cast<const float4*>(&h2f[s * 32 + d0]);
            float4 b = *reinterpret_cast<const float4*>(&h2f[s * 32 + d0 + 2]);
            u64 x[4] = {pack2(a.x, a.y), pack2(a.z, a.w),
                        pack2(b.x, b.y), pack2(b.z, b.w)};
#pragma unroll
            for (int j = 0; j < 4; j++) {
                qa[s] = fma2(x[j], wq[j], qa[s]);
                ka[s] = fma2(x[j], wk[j], ka[s]);
                va[s] = fma2(x[j], wv[j], va[s]);
            }
        }
    }
    {
        u64 scl = dup2(0.35355339059327373f);
#pragma unroll
        for (int s = 0; s < S; s++) qa[s] = mul2(qa[s], scl);
    }

    // ---------------- attention: two head-pair passes, shuffle-free ---------
    const int qi = (lane >> 1) > 10 ? 10 : (lane >> 1);
    const int hl = lane & 1;
    const int hb = hl * 8;
#pragma unroll
    for (int p = 0; p < 2; p++) {
        if ((lane >> 4) == p) {
            int ld = lane & 15;
#pragma unroll
            for (int s = 0; s < S; s++) {
                stg[F2_QS + s * 16 + ld] = qa[s];
                stg[F2_KS + s * 16 + ld] = ka[s];
                stg[F2_VS + s * 16 + ld] = va[s];
            }
        }
        __syncwarp();

        u64 qr[8];
#pragma unroll
        for (int j = 0; j < 8; j += 2) {
            float4 t = *reinterpret_cast<const float4*>(&stf[F2_QS + qi * 16 + hb + j]);
            qr[j] = pack2(t.x, t.y); qr[j + 1] = pack2(t.z, t.w);
        }
        float e0[S], e1[S];
#pragma unroll
        for (int ki = 0; ki < S; ki++) {
            u64 acc = pack2(0.f, 0.f);
#pragma unroll
            for (int j = 0; j < 8; j += 2) {
                float4 kv = *reinterpret_cast<const float4*>(&stf[F2_KS + ki * 16 + hb + j]);
                acc = fma2(qr[j],     pack2(kv.x, kv.y), acc);
                acc = fma2(qr[j + 1], pack2(kv.z, kv.w), acc);
            }
            unpack2(acc, e0[ki], e1[ki]);
        }
        float m0 = e0[0], m1 = e1[0];
#pragma unroll
        for (int ki = 1; ki < S; ki++) { m0 = fmaxf(m0, e0[ki]); m1 = fmaxf(m1, e1[ki]); }
        float den0 = 0.f, den1 = 0.f;
#pragma unroll
        for (int ki = 0; ki < S; ki++) {
            e0[ki] = __expf(e0[ki] - m0); den0 += e0[ki];
            e1[ki] = __expf(e1[ki] - m1); den1 += e1[ki];
        }
        u64 cacc[8];
#pragma unroll
        for (int j = 0; j < 8; j++) cacc[j] = pack2(0.f, 0.f);
#pragma unroll
        for (int ki = 0; ki < S; ki++) {
            u64 ev = pack2(e0[ki], e1[ki]);
#pragma unroll
            for (int j = 0; j < 8; j += 2) {
                float4 vv = *reinterpret_cast<const float4*>(&stf[F2_VS + ki * 16 + hb + j]);
                cacc[j]     = fma2(ev, pack2(vv.x, vv.y), cacc[j]);
                cacc[j + 1] = fma2(ev, pack2(vv.z, vv.w), cacc[j + 1]);
            }
        }
        if (lane < 22) {
            u64 inv = pack2(1.0f / den0, 1.0f / den1);
            int cb = F2_CTX + qi * CTX_STR + (p * 2 + hl) * 8;
#pragma unroll
            for (int j = 0; j < 8; j++) stg[cb + j] = mul2(cacc[j], inv);
        }
        __syncwarp();
    }

    // ---------------- output projection + residual + LN_A (unsplit) ---------
    u64 o[S];
    {
        u64 bo = dup2(W[O_OUTB + lane]);
#pragma unroll
        for (int s = 0; s < S; s++) o[s] = bo;
    }
    for (int d0 = 0; d0 < 32; d0 += 4) {
        float4 fw = *reinterpret_cast<const float4*>(&W[O_OUTW + lane * OUTW_STR + d0]);
        u64 w0 = dup2(fw.x), w1 = dup2(fw.y), w2 = dup2(fw.z), w3 = dup2(fw.w);
#pragma unroll
        for (int s = 0; s < S; s++) {
            float4 c0 = *reinterpret_cast<const float4*>(&stf[F2_CTX + s * CTX_STR + d0]);
            float4 c1 = *reinterpret_cast<const float4*>(&stf[F2_CTX + s * CTX_STR + d0 + 2]);
            o[s] = fma2(pack2(c0.x, c0.y), w0, o[s]);
            o[s] = fma2(pack2(c0.z, c0.w), w1, o[s]);
            o[s] = fma2(pack2(c1.x, c1.y), w2, o[s]);
            o[s] = fma2(pack2(c1.z, c1.w), w3, o[s]);
        }
    }
#pragma unroll
    for (int s = 0; s < S; s++)
        o[s] = add2(o[s], h2u[s * 32 + lane]);
    __syncwarp();
    ln_apply<S>(h2u, 0, stg + F2_CTX,
                o, dup2(W[O_LNAG + lane]), dup2(W[O_LNAB + lane]), lane);

    ffn_pass<0, 6>(h2u, stg, W, lane);
    ffn_pass<6, 5>(h2u, stg, W, lane);
}

// Block 2: CLS-specialized — K/V for all tokens; V stays in registers.
// Out-proj and FFN2 split-half with scalar partials (no register pressure).
__device__ __noinline__ void block2_pair(int hoff, int soff, int lane)
{
    u64* h2u = reinterpret_cast<u64*>(&smem[hoff]);
    u64* stg = reinterpret_cast<u64*>(&smem[soff]);
    const float2* h2f = reinterpret_cast<const float2*>(h2u);
    const float2* stf = reinterpret_cast<const float2*>(stg);
    const float* W = &smem[O_BLKW];

    // ---------------- QKV: k,v all tokens; q token 0 only -------------------
    u64 ka[S], va[S];
    u64 q0 = dup2(W[O_QKVB + lane]);
    {
        u64 bk = dup2(W[O_QKVB + 32 + lane]);
        u64 bv = dup2(W[O_QKVB + 64 + lane]);
#pragma unroll
        for (int s = 0; s < S; s++) { ka[s] = bk; va[s] = bv; }
    }
    for (int d0 = 0; d0 < 32; d0 += 4) {
        float4 fq = *reinterpret_cast<const float4*>(&W[O_QKVW + lane * QKVW_STR + d0]);
        float4 fk = *reinterpret_cast<const float4*>(&W[O_QKVW + (lane + 32) * QKVW_STR + d0]);
        float4 fv = *reinterpret_cast<const float4*>(&W[O_QKVW + (lane + 64) * QKVW_STR + d0]);
        u64 wq[4] = {dup2(fq.x), dup2(fq.y), dup2(fq.z), dup2(fq.w)};
        u64 wk[4] = {dup2(fk.x), dup2(fk.y), dup2(fk.z), dup2(fk.w)};
        u64 wv[4] = {dup2(fv.x), dup2(fv.y), dup2(fv.z), dup2(fv.w)};
#pragma unroll
        for (int s = 0; s < S; s++) {
            float4 a = *reinterpret_cast<const float4*>(&h2f[s * 32 + d0]);
            float4 b = *reinterpret_cast<const float4*>(&h2f[s * 32 + d0 + 2]);
            u64 x[4] = {pack2(a.x, a.y), pack2(a.z, a.w),
                        pack2(b.x, b.y), pack2(b.z, b.w)};
#pragma unroll
            for (int j = 0; j < 4; j++) {
                ka[s] = fma2(x[j], wk[j], ka[s]);
                va[s] = fma2(x[j], wv[j], va[s]);
            }
            if (s == 0) {
#pragma unroll
                for (int j = 0; j < 4; j++) q0 = fma2(x[j], wq[j], q0);
            }
        }
    }
    q0 = mul2(q0, dup2(0.35355339059327373f));

    // stage q0 / K only (lane = dim); V stays in registers
    stg[F2_Q2 + lane] = q0;
#pragma unroll
    for (int s = 0; s < S; s++)
        stg[F2_K2 + s * 32 + lane] = ka[s];
    __syncwarp();

    // ---------------- attention row 0: lane = dim, head = lane>>3 -----------
    const int hb2 = (lane >> 3) * 8;
    u64 qr[8];
#pragma unroll
    for (int j = 0; j < 8; j += 2) {
        float4 t = *reinterpret_cast<const float4*>(&stf[F2_Q2 + hb2 + j]);
        qr[j] = pack2(t.x, t.y); qr[j + 1] = pack2(t.z, t.w);
    }
    float e0[S], e1[S];
#pragma unroll
    for (int ki = 0; ki < S; ki++) {
        u64 acc = pack2(0.f, 0.f);
#pragma unroll
        for (int j = 0; j < 8; j += 2) {
            float4 kv = *reinterpret_cast<const float4*>(&stf[F2_K2 + ki * 32 + hb2 + j]);
            acc = fma2(qr[j],     pack2(kv.x, kv.y), acc);
            acc = fma2(qr[j + 1], pack2(kv.z, kv.w), acc);
        }
        unpack2(acc, e0[ki], e1[ki]);
    }
    float m0 = e0[0], m1 = e1[0];
#pragma unroll
    for (int ki = 1; ki < S; ki++) { m0 = fmaxf(m0, e0[ki]); m1 = fmaxf(m1, e1[ki]); }
    float den0 = 0.f, den1 = 0.f;
#pragma unroll
    for (int ki = 0; ki < S; ki++) {
        e0[ki] = __expf(e0[ki] - m0); den0 += e0[ki];
        e1[ki] = __expf(e1[ki] - m1); den1 += e1[ki];
    }
    u64 c = pack2(0.f, 0.f);
#pragma unroll
    for (int ki = 0; ki < S; ki++)
        c = fma2(pack2(e0[ki], e1[ki]), va[ki], c);    // V from registers
    c = mul2(c, pack2(1.0f / den0, 1.0f / den1));
    stg[F2_C2 + lane] = c;
    __syncwarp();

    // ------------- out-proj token 0 (split-half, scalar partials) -----------
    u64 hn;
    {
        const int g  = lane >> 4;
        const int lg = lane & 15;
        u64 p0 = 0ull, p1 = 0ull;
        const float* owa = &W[O_OUTW + lg * OUTW_STR + g * 16];
        const float* owb = &W[O_OUTW + (lg + 16) * OUTW_STR + g * 16];
        for (int dd = 0; dd < 16; dd += 4) {
            float4 wa = *reinterpret_cast<const float4*>(&owa[dd]);
            float4 wb = *reinterpret_cast<const float4*>(&owb[dd]);
            float4 c0 = *reinterpret_cast<const float4*>(&stf[F2_C2 + g * 16 + dd]);
            float4 c1 = *reinterpret_cast<const float4*>(&stf[F2_C2 + g * 16 + dd + 2]);
            u64 x0 = pack2(c0.x, c0.y), x1 = pack2(c0.z, c0.w);
            u64 x2 = pack2(c1.x, c1.y), x3 = pack2(c1.z, c1.w);
            p0 = fma2(x0, dup2(wa.x), p0); p0 = fma2(x1, dup2(wa.y), p0);
            p0 = fma2(x2, dup2(wa.z), p0); p0 = fma2(x3, dup2(wa.w), p0);
            p1 = fma2(x0, dup2(wb.x), p1); p1 = fma2(x1, dup2(wb.y), p1);
            p1 = fma2(x2, dup2(wb.z), p1); p1 = fma2(x3, dup2(wb.w), p1);
        }
        u64 r0 = add2(p0, shflx2(p0, 16));
        u64 r1 = add2(p1, shflx2(p1, 16));
        u64 o = add2(add2((lane < 16) ? r0 : r1, dup2(W[O_OUTB + lane])),
                     h2u[lane]);
        hn = ln_norm(o, dup2(W[O_LNAG + lane]), dup2(W[O_LNAB + lane]));
        h2u[lane] = hn;
    }
    __syncwarp();

    // ---------------- FFN token 0 -------------------------------------------
    u64 ga[4];
#pragma unroll
    for (int j = 0; j < 4; j++) ga[j] = dup2(W[O_B1 + lane + 32 * j]);
    for (int d0 = 0; d0 < 32; d0 += 4) {
        float4 a = *reinterpret_cast<const float4*>(&h2f[d0]);
        float4 b = *reinterpret_cast<const float4*>(&h2f[d0 + 2]);
        u64 x[4] = {pack2(a.x, a.y), pack2(a.z, a.w),
                    pack2(b.x, b.y), pack2(b.z, b.w)};
#pragma unroll
        for (int j = 0; j < 4; j++) {
            float4 f = *reinterpret_cast<const float4*>(
                &W[O_W1 + (lane + 32 * j) * W1_STR + d0]);
            ga[j] = fma2(x[0], dup2(f.x), ga[j]);
            ga[j] = fma2(x[1], dup2(f.y), ga[j]);
            ga[j] = fma2(x[2], dup2(f.z), ga[j]);
            ga[j] = fma2(x[3], dup2(f.w), ga[j]);
        }
    }
#pragma unroll
    for (int j = 0; j < 4; j++) {
        float a, b; unpack2(ga[j], a, b);
        stg[F2_G2 + lane + 32 * j] = pack2(gelu1(a), gelu1(b));
    }
    __syncwarp();

    // ---- FFN2 token 0, split-half (scalar partials) ----
    {
        const int g  = lane >> 4;
        const int lg = lane & 15;
        u64 p0 = 0ull, p1 = 0ull;
        const float*  w2a = &W[O_W2 + lg * W2_STR + g * 64];
        const float*  w2b = &W[O_W2 + (lg + 16) * W2_STR + g * 64];
        const float2* gh  = &stf[F2_G2 + g * 64];
        for (int fo = 0; fo < 64; fo += 4) {
            float4 wa = *reinterpret_cast<const float4*>(&w2a[fo]);
            float4 wb = *reinterpret_cast<const float4*>(&w2b[fo]);
            float4 a = *reinterpret_cast<const float4*>(&gh[fo]);
            float4 b = *reinterpret_cast<const float4*>(&gh[fo + 2]);
            u64 x0 = pack2(a.x, a.y), x1 = pack2(a.z, a.w);
            u64 x2 = pack2(b.x, b.y), x3 = pack2(b.z, b.w);
            p0 = fma2(x0, dup2(wa.x), p0); p0 = fma2(x1, dup2(wa.y), p0);
            p0 = fma2(x2, dup2(wa.z), p0); p0 = fma2(x3, dup2(wa.w), p0);
            p1 = fma2(x0, dup2(wb.x), p1); p1 = fma2(x1, dup2(wb.y), p1);
            p1 = fma2(x2, dup2(wb.z), p1); p1 = fma2(x3, dup2(wb.w), p1);
        }
        u64 r0 = add2(p0, shflx2(p0, 16));
        u64 r1 = add2(p1, shflx2(p1, 16));
        u64 o2 = add2(add2((lane < 16) ? r0 : r1, dup2(W[O_B2 + lane])), hn);
        h2u[lane] = ln_norm(o2, dup2(W[O_LNBG + lane]), dup2(W[O_LNBB + lane]));
    }
    __syncwarp();
}

__global__ void __launch_bounds__(THREADS)
tab_transformer_kernel(KParams p)
{
    const int tid = threadIdx.x;

    for (int i = tid; i < 320; i += THREADS) smem[O_WFEAT + i] = p.in[1][i];
    for (int i = tid; i < 320; i += THREADS) smem[O_BFEAT + i] = p.in[2][i];
    if (tid < 32) {
        smem[O_CLS  + tid] = p.in[3][tid];
        smem[O_CLFW + tid] = p.in[28][tid];
    }
    if (tid == 0) smem[O_CLFB] = p.in[29][0];
    stage_block(&smem[O_BLKW], &p.in[4], tid);
    __syncthreads();

    const int warp = tid >> 5, lane = tid & 31;
    int pr = blockIdx.x * NW + warp;
    const bool valid = (pr < NPAIR);
    if (!valid) pr = NPAIR - 1;
    const int b0 = pr * 2;

    const int hoff = O_ACT + warp * ACT_F;
    const int soff = hoff + H2_F;
    u64* h2u = reinterpret_cast<u64*>(&smem[hoff]);

    float xv0 = (lane < 10) ? p.in[0][(size_t)b0 * 10 + lane] : 0.f;
    float xv1 = (lane < 10) ? p.in[0][(size_t)(b0 + 1) * 10 + lane] : 0.f;
    h2u[lane] = dup2(smem[O_CLS + lane]);
#pragma unroll
    for (int i = 0; i < 10; i++) {
        float a = __shfl_sync(0xffffffffu, xv0, i);
        float b = __shfl_sync(0xffffffffu, xv1, i);
        u64 w  = dup2(smem[O_WFEAT + i * 32 + lane]);
        u64 bb = dup2(smem[O_BFEAT + i * 32 + lane]);
        h2u[(i + 1) * 32 + lane] = fma2(pack2(a, b), w, bb);
    }
    __syncwarp();

    block_pair(hoff, soff, lane);

    __syncthreads();
    stage_block(&smem[O_BLKW], &p.in[16], tid);
    __syncthreads();

    block2_pair(hoff, soff, lane);

    u64 v = mul2(h2u[lane], dup2(smem[O_CLFW + lane]));
#pragma unroll
    for (int mk = 16; mk; mk >>= 1) v = add2(v, shflx2(v, mk));
    if (valid && lane == 0) {
        float r0, r1; unpack2(v, r0, r1);
        float cb = smem[O_CLFB];
        *reinterpret_cast<float2*>(&p.out[b0]) = make_float2(r0 + cb, r1 + cb);
    }
}

extern "C" void kernel_launch(void* const* d_in, const int* in_sizes, int n_in,
                              void* d_out, int out_size)
{
    (void)in_sizes; (void)n_in; (void)out_size;
    KParams p;
    for (int i = 0; i < 30; i++) p.in[i] = (const float*)d_in[i];
    p.out = (float*)d_out;

    cudaFuncSetAttribute(tab_transformer_kernel,
                         cudaFuncAttributeMaxDynamicSharedMemorySize, SMEM_BYTES);

    const int grid = (NPAIR + NW - 1) / NW;   // 4096
    tab_transformer_kernel<<<grid, THREADS, SMEM_BYTES>>>(p);
}